// round 11
// baseline (speedup 1.0000x reference)
#include <cuda_runtime.h>
#include <cuda_fp16.h>
#include <math.h>

#define BATCH 2
#define SEQ 2048
#define DIM 1024
#define HEADS 16
#define HEAD_DIM 64
#define BS (BATCH * SEQ)
#define QSCL 0.18033688011112042f   // 0.125 * log2(e)

// ---------------- scratch (static device memory; no allocations) ----------------
__device__ float g_x[BS * DIM];
__device__ float g_wq[DIM * DIM];
__device__ float g_wk[DIM * DIM];
__device__ float g_wv[DIM * DIM];
__device__ float g_wo[DIM * DIM];
__device__ float g_q[BS * DIM];            // pre-scaled by 0.125*log2e (log2 domain)
__device__ float g_k[BS * DIM];
__device__ float g_v[BS * DIM];
__device__ float g_ho[BS * DIM];
__device__ float g_l[BATCH * HEADS * SEQ];
__device__ __half g_p[(size_t)BATCH * HEADS * SEQ * SEQ];   // 268 MB fp16 P

// ---------------- helpers --------------------------------------------------------
__device__ __forceinline__ unsigned f2tf(float f) {
    unsigned r;
    asm("cvt.rna.tf32.f32 %0, %1;" : "=r"(r) : "f"(f));
    return r;
}
__device__ __forceinline__ float rndf(float f) { return __uint_as_float(f2tf(f)); }
__device__ __forceinline__ float ex2(float x) {
    float r; asm("ex2.approx.ftz.f32 %0, %1;" : "=f"(r) : "f"(x)); return r;
}

__device__ __forceinline__ void mma_tf32(float c[4], unsigned a0, unsigned a1,
                                         unsigned a2, unsigned a3,
                                         unsigned b0, unsigned b1) {
    asm volatile(
        "mma.sync.aligned.m16n8k8.row.col.f32.tf32.tf32.f32 "
        "{%0,%1,%2,%3}, {%4,%5,%6,%7}, {%8,%9}, {%0,%1,%2,%3};"
        : "+f"(c[0]), "+f"(c[1]), "+f"(c[2]), "+f"(c[3])
        : "r"(a0), "r"(a1), "r"(a2), "r"(a3), "r"(b0), "r"(b1));
}

__device__ __forceinline__ void cp16(unsigned dst, const void* src) {
    asm volatile("cp.async.cg.shared.global [%0], [%1], 16;" :: "r"(dst), "l"(src));
}
__device__ __forceinline__ void cp_commit() {
    asm volatile("cp.async.commit_group;" ::: "memory");
}
__device__ __forceinline__ void cp_wait1() {
    asm volatile("cp.async.wait_group 1;" ::: "memory");
}
__device__ __forceinline__ void cp_wait0() {
    asm volatile("cp.async.wait_group 0;" ::: "memory");
}
__device__ __forceinline__ unsigned sptr(const void* p) {
    return (unsigned)__cvta_generic_to_shared(p);
}
__device__ __forceinline__ unsigned fu(float f) { return __float_as_uint(f); }

// ================= prepass: RN-round all 5 tensors in one launch =================
#define NX4 (BS * DIM / 4)          // 1048576
#define NW4 (DIM * DIM / 4)         // 262144 = 2^18
#define NTOT4 (NX4 + 4 * NW4)       // 2097152

__global__ __launch_bounds__(256) void round_all(
    const float* __restrict__ x,  const float* __restrict__ wq,
    const float* __restrict__ wk, const float* __restrict__ wv,
    const float* __restrict__ wo) {
    int i = blockIdx.x * 256 + threadIdx.x;
    if (i >= NTOT4) return;
    const float* src; float* dst; int off;
    if (i < NX4) { src = x; dst = g_x; off = i; }
    else {
        int j = i - NX4, w = j >> 18;
        off = j & (NW4 - 1);
        if (w == 0)      { src = wq; dst = g_wq; }
        else if (w == 1) { src = wk; dst = g_wk; }
        else if (w == 2) { src = wv; dst = g_wv; }
        else             { src = wo; dst = g_wo; }
    }
    float4 v = ((const float4*)src)[off];
    v.x = rndf(v.x); v.y = rndf(v.y); v.z = rndf(v.z); v.w = rndf(v.w);
    ((float4*)dst)[off] = v;
}

// ================= GEMM bodies ===================================================
#define PS 36

// QKV fused projection: z selects (W, bias, C). z==0 applies the log2e*0.125 scale.
__global__ __launch_bounds__(256, 2) void proj_qkv(
    const float* __restrict__ A,
    const float* __restrict__ bq, const float* __restrict__ bk,
    const float* __restrict__ bv) {
    extern __shared__ float smem[];
    float* As = smem;
    float* Ws = smem + 2 * 128 * PS;

    const int z = blockIdx.z;
    const float* W; const float* bias; float* C;
    if (z == 0)      { W = g_wq; bias = bq; C = g_q; }
    else if (z == 1) { W = g_wk; bias = bk; C = g_k; }
    else             { W = g_wv; bias = bv; C = g_v; }

    const int tid = threadIdx.x;
    const int wid = tid >> 5, lane = tid & 31;
    const int gid = lane >> 2, tig = lane & 3;
    const int wrow = wid & 3, wcol = wid >> 2;
    const int row0 = blockIdx.y * 128;
    const int col0 = blockIdx.x * 128;

    const unsigned asb = sptr(As), wsb = sptr(Ws);

    auto issue = [&](int t, int s) {
        const float* ap = A + (size_t)row0 * DIM + t * 32;
        const float* wp = W + (size_t)col0 * DIM + t * 32;
        unsigned ad = asb + s * 128 * PS * 4;
        unsigned wd = wsb + s * 128 * PS * 4;
        #pragma unroll
        for (int i = tid; i < 1024; i += 256) {
            int r = i >> 3, c = i & 7;
            cp16(ad + r * PS * 4 + c * 16, ap + (size_t)r * DIM + c * 4);
            cp16(wd + r * PS * 4 + c * 16, wp + (size_t)r * DIM + c * 4);
        }
        cp_commit();
    };

    issue(0, 0);
    issue(1, 1);
    cp_wait1();
    __syncthreads();

    float acc[2][8][4];
    #pragma unroll
    for (int mt = 0; mt < 2; mt++)
        #pragma unroll
        for (int nt = 0; nt < 8; nt++)
            #pragma unroll
            for (int i = 0; i < 4; i++) acc[mt][nt][i] = 0.f;

    for (int it = 0; it < 32; it++) {
        const float* as = As + (it & 1) * 128 * PS;
        const float* ws = Ws + (it & 1) * 128 * PS;
        #pragma unroll
        for (int kk = 0; kk < 4; kk++) {
            unsigned a[2][4];
            const int c = kk * 8 + tig;
            #pragma unroll
            for (int mt = 0; mt < 2; mt++) {
                int r = wrow * 32 + mt * 16 + gid;
                a[mt][0] = fu(as[r * PS + c]);
                a[mt][1] = fu(as[(r + 8) * PS + c]);
                a[mt][2] = fu(as[r * PS + c + 4]);
                a[mt][3] = fu(as[(r + 8) * PS + c + 4]);
            }
            #pragma unroll
            for (int nt = 0; nt < 8; nt++) {
                int n = wcol * 64 + nt * 8 + gid;
                unsigned b0 = fu(ws[n * PS + c]), b1 = fu(ws[n * PS + c + 4]);
                mma_tf32(acc[0][nt], a[0][0], a[0][1], a[0][2], a[0][3], b0, b1);
                mma_tf32(acc[1][nt], a[1][0], a[1][1], a[1][2], a[1][3], b0, b1);
            }
        }
        __syncthreads();
        if (it + 2 < 32) { issue(it + 2, it & 1); cp_wait1(); }
        else cp_wait0();
        __syncthreads();
    }

    #pragma unroll
    for (int mt = 0; mt < 2; mt++) {
        #pragma unroll
        for (int nt = 0; nt < 8; nt++) {
            int m = row0 + wrow * 32 + mt * 16 + gid;
            int n = col0 + wcol * 64 + nt * 8 + tig * 2;
            float b0 = bias[n], b1 = bias[n + 1];
            float v0 = rndf(acc[mt][nt][0] + b0);
            float v1 = rndf(acc[mt][nt][1] + b1);
            float v2 = rndf(acc[mt][nt][2] + b0);
            float v3 = rndf(acc[mt][nt][3] + b1);
            if (z == 0) {
                v0 = rndf(v0 * QSCL); v1 = rndf(v1 * QSCL);
                v2 = rndf(v2 * QSCL); v3 = rndf(v3 * QSCL);
            }
            C[(size_t)m * DIM + n]           = v0;
            C[(size_t)m * DIM + n + 1]       = v1;
            C[(size_t)(m + 8) * DIM + n]     = v2;
            C[(size_t)(m + 8) * DIM + n + 1] = v3;
        }
    }
}

// Output-projection body (final result, no rounding).
__device__ __forceinline__ void proj_out_body(
    float* smem, const float* __restrict__ A, const float* __restrict__ W,
    const float* __restrict__ bias, float* __restrict__ C, int bx, int by) {
    float* As = smem;
    float* Ws = smem + 2 * 128 * PS;

    const int tid = threadIdx.x;
    const int wid = tid >> 5, lane = tid & 31;
    const int gid = lane >> 2, tig = lane & 3;
    const int wrow = wid & 3, wcol = wid >> 2;
    const int row0 = by * 128;
    const int col0 = bx * 128;

    const unsigned asb = sptr(As), wsb = sptr(Ws);

    auto issue = [&](int t, int s) {
        const float* ap = A + (size_t)row0 * DIM + t * 32;
        const float* wp = W + (size_t)col0 * DIM + t * 32;
        unsigned ad = asb + s * 128 * PS * 4;
        unsigned wd = wsb + s * 128 * PS * 4;
        #pragma unroll
        for (int i = tid; i < 1024; i += 256) {
            int r = i >> 3, c = i & 7;
            cp16(ad + r * PS * 4 + c * 16, ap + (size_t)r * DIM + c * 4);
            cp16(wd + r * PS * 4 + c * 16, wp + (size_t)r * DIM + c * 4);
        }
        cp_commit();
    };

    issue(0, 0);
    issue(1, 1);
    cp_wait1();
    __syncthreads();

    float acc[2][8][4];
    #pragma unroll
    for (int mt = 0; mt < 2; mt++)
        #pragma unroll
        for (int nt = 0; nt < 8; nt++)
            #pragma unroll
            for (int i = 0; i < 4; i++) acc[mt][nt][i] = 0.f;

    for (int it = 0; it < 32; it++) {
        const float* as = As + (it & 1) * 128 * PS;
        const float* ws = Ws + (it & 1) * 128 * PS;
        #pragma unroll
        for (int kk = 0; kk < 4; kk++) {
            unsigned a[2][4];
            const int c = kk * 8 + tig;
            #pragma unroll
            for (int mt = 0; mt < 2; mt++) {
                int r = wrow * 32 + mt * 16 + gid;
                a[mt][0] = fu(as[r * PS + c]);
                a[mt][1] = fu(as[(r + 8) * PS + c]);
                a[mt][2] = fu(as[r * PS + c + 4]);
                a[mt][3] = fu(as[(r + 8) * PS + c + 4]);
            }
            #pragma unroll
            for (int nt = 0; nt < 8; nt++) {
                int n = wcol * 64 + nt * 8 + gid;
                unsigned b0 = fu(ws[n * PS + c]), b1 = fu(ws[n * PS + c + 4]);
                mma_tf32(acc[0][nt], a[0][0], a[0][1], a[0][2], a[0][3], b0, b1);
                mma_tf32(acc[1][nt], a[1][0], a[1][1], a[1][2], a[1][3], b0, b1);
            }
        }
        __syncthreads();
        if (it + 2 < 32) { issue(it + 2, it & 1); cp_wait1(); }
        else cp_wait0();
        __syncthreads();
    }

    #pragma unroll
    for (int mt = 0; mt < 2; mt++) {
        #pragma unroll
        for (int nt = 0; nt < 8; nt++) {
            int m = row0 + wrow * 32 + mt * 16 + gid;
            int n = col0 + wcol * 64 + nt * 8 + tig * 2;
            float b0 = bias[n], b1 = bias[n + 1];
            C[(size_t)m * DIM + n]           = acc[mt][nt][0] + b0;
            C[(size_t)m * DIM + n + 1]       = acc[mt][nt][1] + b1;
            C[(size_t)(m + 8) * DIM + n]     = acc[mt][nt][2] + b0;
            C[(size_t)(m + 8) * DIM + n + 1] = acc[mt][nt][3] + b1;
        }
    }
}

// ================= fused flash attention (log2-domain) + fp16 P spill ============
#define KQS 68
#define VQS 72
__global__ __launch_bounds__(256, 2) void flash_kernel() {
    extern __shared__ float smem[];
    float* Qs = smem;                         // [128][68]
    float* Ks = Qs + 128 * KQS;               // 2 x [64][68]
    float* Vs = Ks + 2 * 64 * KQS;            // 2 x [64][72]

    const int tid = threadIdx.x;
    const int wid = tid >> 5, lane = tid & 31;
    const int gid = lane >> 2, tig = lane & 3;
    const int q0 = blockIdx.x * 128;
    const int bh = blockIdx.y;
    const int b = bh / HEADS, h = bh % HEADS;

    const float* qbase = g_q + ((size_t)b * SEQ + q0) * DIM + h * HEAD_DIM;
    const float* kbase = g_k + (size_t)b * SEQ * DIM + h * HEAD_DIM;
    const float* vbase = g_v + (size_t)b * SEQ * DIM + h * HEAD_DIM;

    const unsigned qsb = sptr(Qs), ksb = sptr(Ks), vsb = sptr(Vs);

    auto issue_kv = [&](int kt, int s) {
        const float* kp = kbase + (size_t)kt * 64 * DIM;
        const float* vp = vbase + (size_t)kt * 64 * DIM;
        unsigned kd = ksb + s * 64 * KQS * 4;
        unsigned vd = vsb + s * 64 * VQS * 4;
        #pragma unroll
        for (int i = tid; i < 1024; i += 256) {
            int r = i >> 4, c = i & 15;
            cp16(kd + r * KQS * 4 + c * 16, kp + (size_t)r * DIM + c * 4);
            cp16(vd + r * VQS * 4 + c * 16, vp + (size_t)r * DIM + c * 4);
        }
        cp_commit();
    };

    #pragma unroll
    for (int i = tid; i < 2048; i += 256) {
        int r = i >> 4, c = i & 15;
        cp16(qsb + r * KQS * 4 + c * 16, qbase + (size_t)r * DIM + c * 4);
    }
    issue_kv(0, 0);
    issue_kv(1, 1);
    cp_wait1();
    __syncthreads();

    unsigned qa[8][4];
    {
        int r = wid * 16 + gid;
        #pragma unroll
        for (int kk = 0; kk < 8; kk++) {
            int c = kk * 8 + tig;
            qa[kk][0] = fu(Qs[r * KQS + c]);
            qa[kk][1] = fu(Qs[(r + 8) * KQS + c]);
            qa[kk][2] = fu(Qs[r * KQS + c + 4]);
            qa[kk][3] = fu(Qs[(r + 8) * KQS + c + 4]);
        }
    }

    float oacc[8][4];
    #pragma unroll
    for (int nt = 0; nt < 8; nt++)
        #pragma unroll
        for (int i = 0; i < 4; i++) oacc[nt][i] = 0.f;
    float l0 = 0.f, l1 = 0.f;

    const int s0l = (lane & ~3) | (tig >> 1);
    const int s1l = s0l + 2;
    const bool odd = tig & 1;

    const int rowq = q0 + wid * 16 + gid;
    __half* prow0 = g_p + ((size_t)bh * SEQ + rowq) * SEQ + tig * 2;
    __half* prow1 = prow0 + (size_t)8 * SEQ;

    for (int kt = 0; kt < SEQ / 64; kt++) {
        const float* ks = Ks + (kt & 1) * 64 * KQS;
        const float* vs = Vs + (kt & 1) * 64 * VQS;

        float sacc[8][4];
        #pragma unroll
        for (int nt = 0; nt < 8; nt++)
            #pragma unroll
            for (int i = 0; i < 4; i++) sacc[nt][i] = 0.f;
        #pragma unroll
        for (int kk = 0; kk < 8; kk++) {
            #pragma unroll
            for (int nt = 0; nt < 8; nt++) {
                unsigned b0 = fu(ks[(nt * 8 + gid) * KQS + kk * 8 + tig]);
                unsigned b1 = fu(ks[(nt * 8 + gid) * KQS + kk * 8 + tig + 4]);
                mma_tf32(sacc[nt], qa[kk][0], qa[kk][1], qa[kk][2], qa[kk][3], b0, b1);
            }
        }

        // ---- 2^s + local denominators + fp16 P spill ----
        #pragma unroll
        for (int nt = 0; nt < 8; nt++) {
            float p0 = ex2(sacc[nt][0]);
            float p1 = ex2(sacc[nt][1]);
            float p2 = ex2(sacc[nt][2]);
            float p3 = ex2(sacc[nt][3]);
            l0 += p0 + p1;  l1 += p2 + p3;
            *(__half2*)(prow0 + kt * 64 + nt * 8) = __floats2half2_rn(p0, p1);
            *(__half2*)(prow1 + kt * 64 + nt * 8) = __floats2half2_rn(p2, p3);
            sacc[nt][0] = p0; sacc[nt][1] = p1;
            sacc[nt][2] = p2; sacc[nt][3] = p3;
        }

        // ---- O += P * V (A = P via shfl permute) ----
        #pragma unroll
        for (int kk = 0; kk < 8; kk++) {
            float x0 = __shfl_sync(~0u, sacc[kk][0], s0l);
            float x1 = __shfl_sync(~0u, sacc[kk][1], s0l);
            float y0 = __shfl_sync(~0u, sacc[kk][2], s0l);
            float y1 = __shfl_sync(~0u, sacc[kk][3], s0l);
            float z0 = __shfl_sync(~0u, sacc[kk][0], s1l);
            float z1 = __shfl_sync(~0u, sacc[kk][1], s1l);
            float w0 = __shfl_sync(~0u, sacc[kk][2], s1l);
            float w1 = __shfl_sync(~0u, sacc[kk][3], s1l);
            unsigned a0 = fu(odd ? x1 : x0);
            unsigned a1 = fu(odd ? y1 : y0);
            unsigned a2 = fu(odd ? z1 : z0);
            unsigned a3 = fu(odd ? w1 : w0);
            #pragma unroll
            for (int nt = 0; nt < 8; nt++) {
                unsigned b0 = fu(vs[(kk * 8 + tig) * VQS + nt * 8 + gid]);
                unsigned b1 = fu(vs[(kk * 8 + tig + 4) * VQS + nt * 8 + gid]);
                mma_tf32(oacc[nt], a0, a1, a2, a3, b0, b1);
            }
        }

        __syncthreads();
        if (kt + 2 < SEQ / 64) { issue_kv(kt + 2, kt & 1); cp_wait1(); }
        else cp_wait0();
        __syncthreads();
    }

    l0 += __shfl_xor_sync(~0u, l0, 1);
    l0 += __shfl_xor_sync(~0u, l0, 2);
    l1 += __shfl_xor_sync(~0u, l1, 1);
    l1 += __shfl_xor_sync(~0u, l1, 2);

    const float il0 = 1.f / l0, il1 = 1.f / l1;
    float* orow = g_ho + ((size_t)b * SEQ + rowq) * DIM + h * HEAD_DIM;
    #pragma unroll
    for (int nt = 0; nt < 8; nt++) {
        orow[nt * 8 + 2 * tig]               = rndf(oacc[nt][0] * il0);
        orow[nt * 8 + 2 * tig + 1]           = rndf(oacc[nt][1] * il0);
        orow[8 * DIM + nt * 8 + 2 * tig]     = rndf(oacc[nt][2] * il1);
        orow[8 * DIM + nt * 8 + 2 * tig + 1] = rndf(oacc[nt][3] * il1);
    }
    if (tig == 0) {
        size_t mi = (size_t)bh * SEQ + rowq;
        g_l[mi] = l0;
        g_l[mi + 8] = l1;
    }
}

// ================= tail: proj_out (256 blocks) + streaming mean (4096 blocks) ====
__global__ __launch_bounds__(256, 2) void tail_kernel(
    float* __restrict__ amean, const float* __restrict__ A,
    const float* __restrict__ W, const float* __restrict__ bias,
    float* __restrict__ C) {
    extern __shared__ float smem[];
    if (blockIdx.x < 256) {
        proj_out_body(smem, A, W, bias, C, blockIdx.x & 7, blockIdx.x >> 3);
        return;
    }
    // ---- streaming head-mean: one block per (b, q) row ----
    const int idx = blockIdx.x - 256;
    const int b = idx >> 11;            // SEQ = 2048
    const int q = idx & (SEQ - 1);
    const int tid = threadIdx.x;

    const __half* pb = g_p + ((size_t)(b * HEADS) * SEQ + q) * SEQ + tid * 8;
    const size_t hstride = (size_t)SEQ * SEQ;

    float acc[8];
    #pragma unroll
    for (int i = 0; i < 8; i++) acc[i] = 0.f;

    #pragma unroll
    for (int h = 0; h < HEADS; h++) {
        float w = 1.f / (g_l[(size_t)(b * HEADS + h) * SEQ + q] * 16.f);
        uint4 v = *(const uint4*)(pb + h * hstride);
        float2 f0 = __half22float2(*(__half2*)&v.x);
        float2 f1 = __half22float2(*(__half2*)&v.y);
        float2 f2 = __half22float2(*(__half2*)&v.z);
        float2 f3 = __half22float2(*(__half2*)&v.w);
        acc[0] += f0.x * w; acc[1] += f0.y * w;
        acc[2] += f1.x * w; acc[3] += f1.y * w;
        acc[4] += f2.x * w; acc[5] += f2.y * w;
        acc[6] += f3.x * w; acc[7] += f3.y * w;
    }

    float* arow = amean + ((size_t)b * SEQ + q) * SEQ + tid * 8;
    *(float4*)arow       = make_float4(acc[0], acc[1], acc[2], acc[3]);
    *(float4*)(arow + 4) = make_float4(acc[4], acc[5], acc[6], acc[7]);
}

// ---------------- launch ------------------------------------------------------------
#define PROJ_SMEM (4 * 128 * PS * 4)
#define FLASH_SMEM ((128 * KQS + 2 * 64 * KQS + 2 * 64 * VQS) * 4)

extern "C" void kernel_launch(void* const* d_in, const int* in_sizes, int n_in,
                              void* d_out, int out_size) {
    const float* x  = (const float*)d_in[0];
    const float* wq = (const float*)d_in[1];
    const float* bq = (const float*)d_in[2];
    const float* wk = (const float*)d_in[3];
    const float* bk = (const float*)d_in[4];
    const float* wv = (const float*)d_in[5];
    const float* bv = (const float*)d_in[6];
    const float* wo = (const float*)d_in[7];
    const float* bo = (const float*)d_in[8];

    float* out_o    = (float*)d_out;
    float* out_mean = out_o + (size_t)BS * DIM;

    static float* p_x = nullptr;
    static float* p_wo = nullptr;
    static float* p_ho = nullptr;
    if (!p_x) {
        cudaGetSymbolAddress((void**)&p_x, g_x);
        cudaGetSymbolAddress((void**)&p_wo, g_wo);
        cudaGetSymbolAddress((void**)&p_ho, g_ho);
        cudaFuncSetAttribute(proj_qkv,
                             cudaFuncAttributeMaxDynamicSharedMemorySize, PROJ_SMEM);
        cudaFuncSetAttribute(flash_kernel,
                             cudaFuncAttributeMaxDynamicSharedMemorySize, FLASH_SMEM);
        cudaFuncSetAttribute(tail_kernel,
                             cudaFuncAttributeMaxDynamicSharedMemorySize, PROJ_SMEM);
    }

    round_all<<<(NTOT4 + 255) / 256, 256>>>(x, wq, wk, wv, wo);

    proj_qkv<<<dim3(DIM / 128, BS / 128, 3), 256, PROJ_SMEM>>>(p_x, bq, bk, bv);

    flash_kernel<<<dim3(SEQ / 128, BATCH * HEADS), 256, FLASH_SMEM>>>();

    tail_kernel<<<256 + BS, 256, PROJ_SMEM>>>(out_mean, p_ho, p_wo, bo, out_o);
}

// round 12
// speedup vs baseline: 1.1988x; 1.1988x over previous
#include <cuda_runtime.h>
#include <cuda_bf16.h>
#include <math.h>

#define BATCH 2
#define SEQ 2048
#define DIM 1024
#define HEADS 16
#define HEAD_DIM 64
#define BS (BATCH * SEQ)
#define QSCL 0.18033688011112042f   // 0.125 * log2(e)

// ---------------- scratch (static device memory; no allocations) ----------------
__device__ float g_x[BS * DIM];
__device__ float g_wq[DIM * DIM];
__device__ float g_wk[DIM * DIM];
__device__ float g_wv[DIM * DIM];
__device__ float g_wo[DIM * DIM];
__device__ float g_q[BS * DIM];            // pre-scaled by 0.125*log2e (log2 domain)
__device__ float g_k[BS * DIM];
__device__ __nv_bfloat16 g_vt[(size_t)BATCH * HEADS * HEAD_DIM * SEQ];  // V^T bf16
__device__ float g_ho[BS * DIM];
__device__ float g_l[BATCH * HEADS * SEQ];

// ---------------- helpers --------------------------------------------------------
__device__ __forceinline__ unsigned f2tf(float f) {
    unsigned r;
    asm("cvt.rna.tf32.f32 %0, %1;" : "=r"(r) : "f"(f));
    return r;
}
__device__ __forceinline__ float rndf(float f) { return __uint_as_float(f2tf(f)); }
__device__ __forceinline__ float ex2(float x) {
    float r; asm("ex2.approx.ftz.f32 %0, %1;" : "=f"(r) : "f"(x)); return r;
}
__device__ __forceinline__ float lg2(float x) {
    float r; asm("lg2.approx.ftz.f32 %0, %1;" : "=f"(r) : "f"(x)); return r;
}
__device__ __forceinline__ unsigned packbf(float hi, float lo) {
    unsigned r;
    asm("cvt.rn.bf16x2.f32 %0, %1, %2;" : "=r"(r) : "f"(hi), "f"(lo));
    return r;
}

__device__ __forceinline__ void mma_tf32(float c[4], unsigned a0, unsigned a1,
                                         unsigned a2, unsigned a3,
                                         unsigned b0, unsigned b1) {
    asm volatile(
        "mma.sync.aligned.m16n8k8.row.col.f32.tf32.tf32.f32 "
        "{%0,%1,%2,%3}, {%4,%5,%6,%7}, {%8,%9}, {%0,%1,%2,%3};"
        : "+f"(c[0]), "+f"(c[1]), "+f"(c[2]), "+f"(c[3])
        : "r"(a0), "r"(a1), "r"(a2), "r"(a3), "r"(b0), "r"(b1));
}

__device__ __forceinline__ void mma_bf16(float c[4], unsigned a0, unsigned a1,
                                         unsigned a2, unsigned a3,
                                         unsigned b0, unsigned b1) {
    asm volatile(
        "mma.sync.aligned.m16n8k16.row.col.f32.bf16.bf16.f32 "
        "{%0,%1,%2,%3}, {%4,%5,%6,%7}, {%8,%9}, {%0,%1,%2,%3};"
        : "+f"(c[0]), "+f"(c[1]), "+f"(c[2]), "+f"(c[3])
        : "r"(a0), "r"(a1), "r"(a2), "r"(a3), "r"(b0), "r"(b1));
}

__device__ __forceinline__ void cp16(unsigned dst, const void* src) {
    asm volatile("cp.async.cg.shared.global [%0], [%1], 16;" :: "r"(dst), "l"(src));
}
__device__ __forceinline__ void cp_commit() {
    asm volatile("cp.async.commit_group;" ::: "memory");
}
__device__ __forceinline__ void cp_wait1() {
    asm volatile("cp.async.wait_group 1;" ::: "memory");
}
__device__ __forceinline__ void cp_wait0() {
    asm volatile("cp.async.wait_group 0;" ::: "memory");
}
__device__ __forceinline__ unsigned sptr(const void* p) {
    return (unsigned)__cvta_generic_to_shared(p);
}
__device__ __forceinline__ unsigned fu(float f) { return __float_as_uint(f); }

// ================= prepass: RN-round all 5 tensors in one launch =================
#define NX4 (BS * DIM / 4)          // 1048576
#define NW4 (DIM * DIM / 4)         // 262144 = 2^18
#define NTOT4 (NX4 + 4 * NW4)

__global__ __launch_bounds__(256) void round_all(
    const float* __restrict__ x,  const float* __restrict__ wq,
    const float* __restrict__ wk, const float* __restrict__ wv,
    const float* __restrict__ wo) {
    int i = blockIdx.x * 256 + threadIdx.x;
    if (i >= NTOT4) return;
    const float* src; float* dst; int off;
    if (i < NX4) { src = x; dst = g_x; off = i; }
    else {
        int j = i - NX4, w = j >> 18;
        off = j & (NW4 - 1);
        if (w == 0)      { src = wq; dst = g_wq; }
        else if (w == 1) { src = wk; dst = g_wk; }
        else if (w == 2) { src = wv; dst = g_wv; }
        else             { src = wo; dst = g_wo; }
    }
    float4 v = ((const float4*)src)[off];
    v.x = rndf(v.x); v.y = rndf(v.y); v.z = rndf(v.z); v.w = rndf(v.w);
    ((float4*)dst)[off] = v;
}

// ================= GEMM bodies ===================================================
#define PS 36

// QKV fused projection. z==0: Q (scaled, log2 domain). z==1: K. z==2: V -> g_vt bf16 transposed.
__global__ __launch_bounds__(256, 2) void proj_qkv(
    const float* __restrict__ A,
    const float* __restrict__ bq, const float* __restrict__ bk,
    const float* __restrict__ bv) {
    extern __shared__ float smem[];
    float* As = smem;
    float* Ws = smem + 2 * 128 * PS;

    const int z = blockIdx.z;
    const float* W; const float* bias; float* C;
    if (z == 0)      { W = g_wq; bias = bq; C = g_q; }
    else if (z == 1) { W = g_wk; bias = bk; C = g_k; }
    else             { W = g_wv; bias = bv; C = nullptr; }

    const int tid = threadIdx.x;
    const int wid = tid >> 5, lane = tid & 31;
    const int gid = lane >> 2, tig = lane & 3;
    const int wrow = wid & 3, wcol = wid >> 2;
    const int row0 = blockIdx.y * 128;
    const int col0 = blockIdx.x * 128;

    const unsigned asb = sptr(As), wsb = sptr(Ws);

    auto issue = [&](int t, int s) {
        const float* ap = A + (size_t)row0 * DIM + t * 32;
        const float* wp = W + (size_t)col0 * DIM + t * 32;
        unsigned ad = asb + s * 128 * PS * 4;
        unsigned wd = wsb + s * 128 * PS * 4;
        #pragma unroll
        for (int i = tid; i < 1024; i += 256) {
            int r = i >> 3, c = i & 7;
            cp16(ad + r * PS * 4 + c * 16, ap + (size_t)r * DIM + c * 4);
            cp16(wd + r * PS * 4 + c * 16, wp + (size_t)r * DIM + c * 4);
        }
        cp_commit();
    };

    issue(0, 0);
    issue(1, 1);
    cp_wait1();
    __syncthreads();

    float acc[2][8][4];
    #pragma unroll
    for (int mt = 0; mt < 2; mt++)
        #pragma unroll
        for (int nt = 0; nt < 8; nt++)
            #pragma unroll
            for (int i = 0; i < 4; i++) acc[mt][nt][i] = 0.f;

    for (int it = 0; it < 32; it++) {
        const float* as = As + (it & 1) * 128 * PS;
        const float* ws = Ws + (it & 1) * 128 * PS;
        #pragma unroll
        for (int kk = 0; kk < 4; kk++) {
            unsigned a[2][4];
            const int c = kk * 8 + tig;
            #pragma unroll
            for (int mt = 0; mt < 2; mt++) {
                int r = wrow * 32 + mt * 16 + gid;
                a[mt][0] = fu(as[r * PS + c]);
                a[mt][1] = fu(as[(r + 8) * PS + c]);
                a[mt][2] = fu(as[r * PS + c + 4]);
                a[mt][3] = fu(as[(r + 8) * PS + c + 4]);
            }
            #pragma unroll
            for (int nt = 0; nt < 8; nt++) {
                int n = wcol * 64 + nt * 8 + gid;
                unsigned b0 = fu(ws[n * PS + c]), b1 = fu(ws[n * PS + c + 4]);
                mma_tf32(acc[0][nt], a[0][0], a[0][1], a[0][2], a[0][3], b0, b1);
                mma_tf32(acc[1][nt], a[1][0], a[1][1], a[1][2], a[1][3], b0, b1);
            }
        }
        __syncthreads();
        if (it + 2 < 32) { issue(it + 2, it & 1); cp_wait1(); }
        else cp_wait0();
        __syncthreads();
    }

    #pragma unroll
    for (int mt = 0; mt < 2; mt++) {
        #pragma unroll
        for (int nt = 0; nt < 8; nt++) {
            int m = row0 + wrow * 32 + mt * 16 + gid;
            int n = col0 + wcol * 64 + nt * 8 + tig * 2;
            float b0 = bias[n], b1 = bias[n + 1];
            float v0 = acc[mt][nt][0] + b0;
            float v1 = acc[mt][nt][1] + b1;
            float v2 = acc[mt][nt][2] + b0;
            float v3 = acc[mt][nt][3] + b1;
            if (z == 2) {
                // V: store transposed bf16  g_vt[(b*H + h)*64 + d][s]
                int bb = m >> 11, s = m & (SEQ - 1);
                int h = n >> 6, d = n & 63;
                size_t base = ((size_t)(bb * HEADS + h) * HEAD_DIM + d) * SEQ;
                g_vt[base + s]                 = __float2bfloat16(v0);
                g_vt[base + SEQ + s]           = __float2bfloat16(v1);   // d+1
                g_vt[base + s + 8]             = __float2bfloat16(v2);   // m+8
                g_vt[base + SEQ + s + 8]       = __float2bfloat16(v3);
            } else {
                v0 = rndf(v0); v1 = rndf(v1); v2 = rndf(v2); v3 = rndf(v3);
                if (z == 0) {
                    v0 = rndf(v0 * QSCL); v1 = rndf(v1 * QSCL);
                    v2 = rndf(v2 * QSCL); v3 = rndf(v3 * QSCL);
                }
                C[(size_t)m * DIM + n]           = v0;
                C[(size_t)m * DIM + n + 1]       = v1;
                C[(size_t)(m + 8) * DIM + n]     = v2;
                C[(size_t)(m + 8) * DIM + n + 1] = v3;
            }
        }
    }
}

// Output-projection body (final result, no rounding).
__device__ __forceinline__ void proj_out_body(
    float* smem, const float* __restrict__ A, const float* __restrict__ W,
    const float* __restrict__ bias, float* __restrict__ C, int bx, int by) {
    float* As = smem;
    float* Ws = smem + 2 * 128 * PS;

    const int tid = threadIdx.x;
    const int wid = tid >> 5, lane = tid & 31;
    const int gid = lane >> 2, tig = lane & 3;
    const int wrow = wid & 3, wcol = wid >> 2;
    const int row0 = by * 128;
    const int col0 = bx * 128;

    const unsigned asb = sptr(As), wsb = sptr(Ws);

    auto issue = [&](int t, int s) {
        const float* ap = A + (size_t)row0 * DIM + t * 32;
        const float* wp = W + (size_t)col0 * DIM + t * 32;
        unsigned ad = asb + s * 128 * PS * 4;
        unsigned wd = wsb + s * 128 * PS * 4;
        #pragma unroll
        for (int i = tid; i < 1024; i += 256) {
            int r = i >> 3, c = i & 7;
            cp16(ad + r * PS * 4 + c * 16, ap + (size_t)r * DIM + c * 4);
            cp16(wd + r * PS * 4 + c * 16, wp + (size_t)r * DIM + c * 4);
        }
        cp_commit();
    };

    issue(0, 0);
    issue(1, 1);
    cp_wait1();
    __syncthreads();

    float acc[2][8][4];
    #pragma unroll
    for (int mt = 0; mt < 2; mt++)
        #pragma unroll
        for (int nt = 0; nt < 8; nt++)
            #pragma unroll
            for (int i = 0; i < 4; i++) acc[mt][nt][i] = 0.f;

    for (int it = 0; it < 32; it++) {
        const float* as = As + (it & 1) * 128 * PS;
        const float* ws = Ws + (it & 1) * 128 * PS;
        #pragma unroll
        for (int kk = 0; kk < 4; kk++) {
            unsigned a[2][4];
            const int c = kk * 8 + tig;
            #pragma unroll
            for (int mt = 0; mt < 2; mt++) {
                int r = wrow * 32 + mt * 16 + gid;
                a[mt][0] = fu(as[r * PS + c]);
                a[mt][1] = fu(as[(r + 8) * PS + c]);
                a[mt][2] = fu(as[r * PS + c + 4]);
                a[mt][3] = fu(as[(r + 8) * PS + c + 4]);
            }
            #pragma unroll
            for (int nt = 0; nt < 8; nt++) {
                int n = wcol * 64 + nt * 8 + gid;
                unsigned b0 = fu(ws[n * PS + c]), b1 = fu(ws[n * PS + c + 4]);
                mma_tf32(acc[0][nt], a[0][0], a[0][1], a[0][2], a[0][3], b0, b1);
                mma_tf32(acc[1][nt], a[1][0], a[1][1], a[1][2], a[1][3], b0, b1);
            }
        }
        __syncthreads();
        if (it + 2 < 32) { issue(it + 2, it & 1); cp_wait1(); }
        else cp_wait0();
        __syncthreads();
    }

    #pragma unroll
    for (int mt = 0; mt < 2; mt++) {
        #pragma unroll
        for (int nt = 0; nt < 8; nt++) {
            int m = row0 + wrow * 32 + mt * 16 + gid;
            int n = col0 + wcol * 64 + nt * 8 + tig * 2;
            float b0 = bias[n], b1 = bias[n + 1];
            C[(size_t)m * DIM + n]           = acc[mt][nt][0] + b0;
            C[(size_t)m * DIM + n + 1]       = acc[mt][nt][1] + b1;
            C[(size_t)(m + 8) * DIM + n]     = acc[mt][nt][2] + b0;
            C[(size_t)(m + 8) * DIM + n + 1] = acc[mt][nt][3] + b1;
        }
    }
}

// ================= fused flash attention: tf32 QK, bf16 PV (no shuffles) =========
#define KQS 68    // floats per K/Q smem row
#define VTS 72    // halves per Vt smem row
__global__ __launch_bounds__(256, 2) void flash_kernel() {
    extern __shared__ float smem[];
    float* Qs = smem;                                   // [128][68] f32
    float* Ks = Qs + 128 * KQS;                         // 2 x [64][68] f32
    __nv_bfloat16* Vt = (__nv_bfloat16*)(Ks + 2 * 64 * KQS);  // 2 x [64][72] bf16

    const int tid = threadIdx.x;
    const int wid = tid >> 5, lane = tid & 31;
    const int gid = lane >> 2, tig = lane & 3;
    const int q0 = blockIdx.x * 128;
    const int bh = blockIdx.y;
    const int b = bh / HEADS, h = bh % HEADS;

    const float* qbase = g_q + ((size_t)b * SEQ + q0) * DIM + h * HEAD_DIM;
    const float* kbase = g_k + (size_t)b * SEQ * DIM + h * HEAD_DIM;
    const __nv_bfloat16* vtbase = g_vt + (size_t)bh * HEAD_DIM * SEQ;

    const unsigned qsb = sptr(Qs), ksb = sptr(Ks), vsb = sptr(Vt);

    auto issue_kv = [&](int kt, int s) {
        const float* kp = kbase + (size_t)kt * 64 * DIM;
        unsigned kd = ksb + s * 64 * KQS * 4;
        #pragma unroll
        for (int i = tid; i < 1024; i += 256) {
            int r = i >> 4, c = i & 15;
            cp16(kd + r * KQS * 4 + c * 16, kp + (size_t)r * DIM + c * 4);
        }
        // Vt: 64 dim-rows x 64 keys bf16 = 128B per row
        const __nv_bfloat16* vp = vtbase + kt * 64;
        unsigned vd = vsb + s * 64 * VTS * 2;
        #pragma unroll
        for (int i = tid; i < 512; i += 256) {
            int r = i >> 3, c = i & 7;
            cp16(vd + r * VTS * 2 + c * 16, vp + (size_t)r * SEQ + c * 8);
        }
        cp_commit();
    };

    #pragma unroll
    for (int i = tid; i < 2048; i += 256) {
        int r = i >> 4, c = i & 15;
        cp16(qsb + r * KQS * 4 + c * 16, qbase + (size_t)r * DIM + c * 4);
    }
    issue_kv(0, 0);
    issue_kv(1, 1);
    cp_wait1();
    __syncthreads();

    unsigned qa[8][4];
    {
        int r = wid * 16 + gid;
        #pragma unroll
        for (int kk = 0; kk < 8; kk++) {
            int c = kk * 8 + tig;
            qa[kk][0] = fu(Qs[r * KQS + c]);
            qa[kk][1] = fu(Qs[(r + 8) * KQS + c]);
            qa[kk][2] = fu(Qs[r * KQS + c + 4]);
            qa[kk][3] = fu(Qs[(r + 8) * KQS + c + 4]);
        }
    }

    float oacc[8][4];
    #pragma unroll
    for (int nt = 0; nt < 8; nt++)
        #pragma unroll
        for (int i = 0; i < 4; i++) oacc[nt][i] = 0.f;
    float l0 = 0.f, l1 = 0.f;

    const int rowq = q0 + wid * 16 + gid;

    for (int kt = 0; kt < SEQ / 64; kt++) {
        const float* ks = Ks + (kt & 1) * 64 * KQS;
        const __nv_bfloat16* vs = Vt + (kt & 1) * 64 * VTS;

        float sacc[8][4];
        #pragma unroll
        for (int nt = 0; nt < 8; nt++)
            #pragma unroll
            for (int i = 0; i < 4; i++) sacc[nt][i] = 0.f;
        #pragma unroll
        for (int kk = 0; kk < 8; kk++) {
            #pragma unroll
            for (int nt = 0; nt < 8; nt++) {
                unsigned b0 = fu(ks[(nt * 8 + gid) * KQS + kk * 8 + tig]);
                unsigned b1 = fu(ks[(nt * 8 + gid) * KQS + kk * 8 + tig + 4]);
                mma_tf32(sacc[nt], qa[kk][0], qa[kk][1], qa[kk][2], qa[kk][3], b0, b1);
            }
        }

        // ---- 2^s, denominators, pack P to bf16x2 (A-fragment layout!) ----
        unsigned pa0[8], pa1[8];
        #pragma unroll
        for (int nt = 0; nt < 8; nt++) {
            float p0 = ex2(sacc[nt][0]);
            float p1 = ex2(sacc[nt][1]);
            float p2 = ex2(sacc[nt][2]);
            float p3 = ex2(sacc[nt][3]);
            l0 += p0 + p1;  l1 += p2 + p3;
            pa0[nt] = packbf(p1, p0);   // row gid:   {lo=k2t, hi=k2t+1}
            pa1[nt] = packbf(p3, p2);   // row gid+8
        }

        // ---- O += P * V via bf16 m16n8k16 (no shuffles) ----
        #pragma unroll
        for (int j = 0; j < 4; j++) {
            unsigned a0 = pa0[2 * j],     a1 = pa1[2 * j];
            unsigned a2 = pa0[2 * j + 1], a3 = pa1[2 * j + 1];
            #pragma unroll
            for (int nt = 0; nt < 8; nt++) {
                const __nv_bfloat16* vrow = vs + (nt * 8 + gid) * VTS + j * 16 + tig * 2;
                unsigned b0 = *(const unsigned*)vrow;
                unsigned b1 = *(const unsigned*)(vrow + 8);
                mma_bf16(oacc[nt], a0, a1, a2, a3, b0, b1);
            }
        }

        __syncthreads();
        if (kt + 2 < SEQ / 64) { issue_kv(kt + 2, kt & 1); cp_wait1(); }
        else cp_wait0();
        __syncthreads();
    }

    l0 += __shfl_xor_sync(~0u, l0, 1);
    l0 += __shfl_xor_sync(~0u, l0, 2);
    l1 += __shfl_xor_sync(~0u, l1, 1);
    l1 += __shfl_xor_sync(~0u, l1, 2);

    const float il0 = 1.f / l0, il1 = 1.f / l1;
    float* orow = g_ho + ((size_t)b * SEQ + rowq) * DIM + h * HEAD_DIM;
    #pragma unroll
    for (int nt = 0; nt < 8; nt++) {
        orow[nt * 8 + 2 * tig]               = rndf(oacc[nt][0] * il0);
        orow[nt * 8 + 2 * tig + 1]           = rndf(oacc[nt][1] * il0);
        orow[8 * DIM + nt * 8 + 2 * tig]     = rndf(oacc[nt][2] * il1);
        orow[8 * DIM + nt * 8 + 2 * tig + 1] = rndf(oacc[nt][3] * il1);
    }
    if (tig == 0) {
        size_t mi = (size_t)bh * SEQ + rowq;
        g_l[mi] = l0;
        g_l[mi + 8] = l1;
    }
}

// ================= head-mean body (tf32 recompute; identical score numerics) =====
#define MQS 68
__device__ __forceinline__ void mean_body(float* smem, float* __restrict__ amean,
                                          int bkx, int bqy, int b) {
    float* Qs = smem;                    // 2 x [128][68]
    float* Ks = smem + 2 * 128 * MQS;    // 2 x [64][68]

    const int tid = threadIdx.x;
    const int wid = tid >> 5, lane = tid & 31;
    const int gid = lane >> 2, tig = lane & 3;
    const int k0 = bkx * 64;
    const int q0 = bqy * 128;

    const float* qbase = g_q + ((size_t)b * SEQ + q0) * DIM;
    const float* kbase = g_k + ((size_t)b * SEQ + k0) * DIM;

    const unsigned qsb = sptr(Qs), ksb = sptr(Ks);

    auto issue_h = [&](int h, int s) {
        const float* qp = qbase + h * HEAD_DIM;
        const float* kp = kbase + h * HEAD_DIM;
        unsigned qd = qsb + s * 128 * MQS * 4;
        unsigned kd = ksb + s * 64 * MQS * 4;
        #pragma unroll
        for (int i = tid; i < 2048; i += 256) {
            int r = i >> 4, c = i & 15;
            cp16(qd + r * MQS * 4 + c * 16, qp + (size_t)r * DIM + c * 4);
        }
        #pragma unroll
        for (int i = tid; i < 1024; i += 256) {
            int r = i >> 4, c = i & 15;
            cp16(kd + r * MQS * 4 + c * 16, kp + (size_t)r * DIM + c * 4);
        }
        cp_commit();
    };

    issue_h(0, 0);
    issue_h(1, 1);
    cp_wait1();
    __syncthreads();

    float amacc[8][4];
    #pragma unroll
    for (int nt = 0; nt < 8; nt++)
        #pragma unroll
        for (int i = 0; i < 4; i++) amacc[nt][i] = 0.f;

    for (int h = 0; h < HEADS; h++) {
        const float* qs = Qs + (h & 1) * 128 * MQS;
        const float* ks = Ks + (h & 1) * 64 * MQS;

        unsigned qa[8][4];
        int r = wid * 16 + gid;
        #pragma unroll
        for (int kk = 0; kk < 8; kk++) {
            int c = kk * 8 + tig;
            qa[kk][0] = fu(qs[r * MQS + c]);
            qa[kk][1] = fu(qs[(r + 8) * MQS + c]);
            qa[kk][2] = fu(qs[r * MQS + c + 4]);
            qa[kk][3] = fu(qs[(r + 8) * MQS + c + 4]);
        }

        float sacc[8][4];
        #pragma unroll
        for (int nt = 0; nt < 8; nt++)
            #pragma unroll
            for (int i = 0; i < 4; i++) sacc[nt][i] = 0.f;
        #pragma unroll
        for (int kk = 0; kk < 8; kk++) {
            #pragma unroll
            for (int nt = 0; nt < 8; nt++) {
                unsigned b0 = fu(ks[(nt * 8 + gid) * MQS + kk * 8 + tig]);
                unsigned b1 = fu(ks[(nt * 8 + gid) * MQS + kk * 8 + tig + 4]);
                mma_tf32(sacc[nt], qa[kk][0], qa[kk][1], qa[kk][2], qa[kk][3], b0, b1);
            }
        }

        size_t mi = ((size_t)(b * HEADS + h)) * SEQ + q0 + wid * 16 + gid;
        float c0 = -lg2(g_l[mi]) - 4.0f;
        float c1 = -lg2(g_l[mi + 8]) - 4.0f;
        #pragma unroll
        for (int nt = 0; nt < 8; nt++) {
            amacc[nt][0] += ex2(sacc[nt][0] + c0);
            amacc[nt][1] += ex2(sacc[nt][1] + c0);
            amacc[nt][2] += ex2(sacc[nt][2] + c1);
            amacc[nt][3] += ex2(sacc[nt][3] + c1);
        }

        __syncthreads();
        if (h + 2 < HEADS) { issue_h(h + 2, h & 1); cp_wait1(); }
        else cp_wait0();
        __syncthreads();
    }

    const int row = q0 + wid * 16 + gid;
    float* arow = amean + ((size_t)b * SEQ + row) * SEQ + k0;
    #pragma unroll
    for (int nt = 0; nt < 8; nt++) {
        arow[nt * 8 + 2 * tig]               = amacc[nt][0];
        arow[nt * 8 + 2 * tig + 1]           = amacc[nt][1];
        arow[8 * SEQ + nt * 8 + 2 * tig]     = amacc[nt][2];
        arow[8 * SEQ + nt * 8 + 2 * tig + 1] = amacc[nt][3];
    }
}

// ================= tail: proj_out (256 blocks) + mean (1024 blocks) ==============
__global__ __launch_bounds__(256, 2) void tail_kernel(
    float* __restrict__ amean, const float* __restrict__ A,
    const float* __restrict__ W, const float* __restrict__ bias,
    float* __restrict__ C) {
    extern __shared__ float smem[];
    if (blockIdx.x < 256) {
        proj_out_body(smem, A, W, bias, C, blockIdx.x & 7, blockIdx.x >> 3);
    } else {
        int bx = blockIdx.x - 256;
        mean_body(smem, amean, bx & 31, (bx >> 5) & 15, bx >> 9);
    }
}

// ---------------- launch ------------------------------------------------------------
#define PROJ_SMEM (4 * 128 * PS * 4)
#define FLASH_SMEM ((128 * KQS + 2 * 64 * KQS) * 4 + 2 * 64 * VTS * 2)
#define MEAN_SMEM ((2 * 128 * MQS + 2 * 64 * MQS) * 4)
#define TAIL_SMEM (MEAN_SMEM > PROJ_SMEM ? MEAN_SMEM : PROJ_SMEM)

extern "C" void kernel_launch(void* const* d_in, const int* in_sizes, int n_in,
                              void* d_out, int out_size) {
    const float* x  = (const float*)d_in[0];
    const float* wq = (const float*)d_in[1];
    const float* bq = (const float*)d_in[2];
    const float* wk = (const float*)d_in[3];
    const float* bk = (const float*)d_in[4];
    const float* wv = (const float*)d_in[5];
    const float* bv = (const float*)d_in[6];
    const float* wo = (const float*)d_in[7];
    const float* bo = (const float*)d_in[8];

    float* out_o    = (float*)d_out;
    float* out_mean = out_o + (size_t)BS * DIM;

    static float* p_x = nullptr;
    static float* p_wo = nullptr;
    static float* p_ho = nullptr;
    if (!p_x) {
        cudaGetSymbolAddress((void**)&p_x, g_x);
        cudaGetSymbolAddress((void**)&p_wo, g_wo);
        cudaGetSymbolAddress((void**)&p_ho, g_ho);
        cudaFuncSetAttribute(proj_qkv,
                             cudaFuncAttributeMaxDynamicSharedMemorySize, PROJ_SMEM);
        cudaFuncSetAttribute(flash_kernel,
                             cudaFuncAttributeMaxDynamicSharedMemorySize, FLASH_SMEM);
        cudaFuncSetAttribute(tail_kernel,
                             cudaFuncAttributeMaxDynamicSharedMemorySize, TAIL_SMEM);
    }

    round_all<<<(NTOT4 + 255) / 256, 256>>>(x, wq, wk, wv, wo);

    proj_qkv<<<dim3(DIM / 128, BS / 128, 3), 256, PROJ_SMEM>>>(p_x, bq, bk, bv);

    flash_kernel<<<dim3(SEQ / 128, BATCH * HEADS), 256, FLASH_SMEM>>>();

    tail_kernel<<<256 + SEQ / 64 * (SEQ / 128) * BATCH, 256, TAIL_SMEM>>>(
        out_mean, p_ho, p_wo, bo, out_o);
}

// round 13
// speedup vs baseline: 1.3379x; 1.1160x over previous
#include <cuda_runtime.h>
#include <cuda_fp16.h>
#include <math.h>

#define BATCH 2
#define SEQ 2048
#define DIM 1024
#define HEADS 16
#define HEAD_DIM 64
#define BS (BATCH * SEQ)
#define QSCL 0.18033688011112042f   // 0.125 * log2(e)

// ---------------- scratch (static device memory; no allocations) ----------------
__device__ float g_x[BS * DIM];
__device__ float g_wq[DIM * DIM];
__device__ float g_wk[DIM * DIM];
__device__ float g_wv[DIM * DIM];
__device__ float g_wo[DIM * DIM];
__device__ float g_q[BS * DIM];            // tf32 grid, log2 domain (pre-scaled)
__device__ float g_k[BS * DIM];
__device__ __half g_qh[BS * DIM];          // fp16 copy of g_q (for mean pass)
__device__ __half g_kh[BS * DIM];          // fp16 copy of g_k
__device__ __half g_vt[(size_t)BATCH * HEADS * HEAD_DIM * SEQ];  // V^T fp16
__device__ float g_ho[BS * DIM];
__device__ float g_l[BATCH * HEADS * SEQ];

// ---------------- helpers --------------------------------------------------------
__device__ __forceinline__ unsigned f2tf(float f) {
    unsigned r;
    asm("cvt.rna.tf32.f32 %0, %1;" : "=r"(r) : "f"(f));
    return r;
}
__device__ __forceinline__ float rndf(float f) { return __uint_as_float(f2tf(f)); }
__device__ __forceinline__ float ex2(float x) {
    float r; asm("ex2.approx.ftz.f32 %0, %1;" : "=f"(r) : "f"(x)); return r;
}
__device__ __forceinline__ float lg2(float x) {
    float r; asm("lg2.approx.ftz.f32 %0, %1;" : "=f"(r) : "f"(x)); return r;
}
__device__ __forceinline__ unsigned packh(float hi, float lo) {
    unsigned r;
    asm("cvt.rn.f16x2.f32 %0, %1, %2;" : "=r"(r) : "f"(hi), "f"(lo));
    return r;
}

__device__ __forceinline__ void mma_tf32(float c[4], unsigned a0, unsigned a1,
                                         unsigned a2, unsigned a3,
                                         unsigned b0, unsigned b1) {
    asm volatile(
        "mma.sync.aligned.m16n8k8.row.col.f32.tf32.tf32.f32 "
        "{%0,%1,%2,%3}, {%4,%5,%6,%7}, {%8,%9}, {%0,%1,%2,%3};"
        : "+f"(c[0]), "+f"(c[1]), "+f"(c[2]), "+f"(c[3])
        : "r"(a0), "r"(a1), "r"(a2), "r"(a3), "r"(b0), "r"(b1));
}

__device__ __forceinline__ void mma_f16(float c[4], unsigned a0, unsigned a1,
                                        unsigned a2, unsigned a3,
                                        unsigned b0, unsigned b1) {
    asm volatile(
        "mma.sync.aligned.m16n8k16.row.col.f32.f16.f16.f32 "
        "{%0,%1,%2,%3}, {%4,%5,%6,%7}, {%8,%9}, {%0,%1,%2,%3};"
        : "+f"(c[0]), "+f"(c[1]), "+f"(c[2]), "+f"(c[3])
        : "r"(a0), "r"(a1), "r"(a2), "r"(a3), "r"(b0), "r"(b1));
}

__device__ __forceinline__ void cp16(unsigned dst, const void* src) {
    asm volatile("cp.async.cg.shared.global [%0], [%1], 16;" :: "r"(dst), "l"(src));
}
__device__ __forceinline__ void cp_commit() {
    asm volatile("cp.async.commit_group;" ::: "memory");
}
__device__ __forceinline__ void cp_wait1() {
    asm volatile("cp.async.wait_group 1;" ::: "memory");
}
__device__ __forceinline__ void cp_wait0() {
    asm volatile("cp.async.wait_group 0;" ::: "memory");
}
__device__ __forceinline__ unsigned sptr(const void* p) {
    return (unsigned)__cvta_generic_to_shared(p);
}
__device__ __forceinline__ unsigned fu(float f) { return __float_as_uint(f); }

// ================= prepass: RN-round all 5 tensors in one launch =================
#define NX4 (BS * DIM / 4)
#define NW4 (DIM * DIM / 4)         // 2^18
#define NTOT4 (NX4 + 4 * NW4)

__global__ __launch_bounds__(256) void round_all(
    const float* __restrict__ x,  const float* __restrict__ wq,
    const float* __restrict__ wk, const float* __restrict__ wv,
    const float* __restrict__ wo) {
    int i = blockIdx.x * 256 + threadIdx.x;
    if (i >= NTOT4) return;
    const float* src; float* dst; int off;
    if (i < NX4) { src = x; dst = g_x; off = i; }
    else {
        int j = i - NX4, w = j >> 18;
        off = j & (NW4 - 1);
        if (w == 0)      { src = wq; dst = g_wq; }
        else if (w == 1) { src = wk; dst = g_wk; }
        else if (w == 2) { src = wv; dst = g_wv; }
        else             { src = wo; dst = g_wo; }
    }
    float4 v = ((const float4*)src)[off];
    v.x = rndf(v.x); v.y = rndf(v.y); v.z = rndf(v.z); v.w = rndf(v.w);
    ((float4*)dst)[off] = v;
}

// ================= GEMM bodies ===================================================
#define PS 36

// QKV fused projection. z==0: Q (scaled, log2) + fp16 copy. z==1: K + fp16 copy.
// z==2: V -> g_vt fp16 transposed.
__global__ __launch_bounds__(256, 2) void proj_qkv(
    const float* __restrict__ A,
    const float* __restrict__ bq, const float* __restrict__ bk,
    const float* __restrict__ bv) {
    extern __shared__ float smem[];
    float* As = smem;
    float* Ws = smem + 2 * 128 * PS;

    const int z = blockIdx.z;
    const float* W; const float* bias; float* C; __half* Ch;
    if (z == 0)      { W = g_wq; bias = bq; C = g_q; Ch = g_qh; }
    else if (z == 1) { W = g_wk; bias = bk; C = g_k; Ch = g_kh; }
    else             { W = g_wv; bias = bv; C = nullptr; Ch = nullptr; }

    const int tid = threadIdx.x;
    const int wid = tid >> 5, lane = tid & 31;
    const int gid = lane >> 2, tig = lane & 3;
    const int wrow = wid & 3, wcol = wid >> 2;
    const int row0 = blockIdx.y * 128;
    const int col0 = blockIdx.x * 128;

    const unsigned asb = sptr(As), wsb = sptr(Ws);

    auto issue = [&](int t, int s) {
        const float* ap = A + (size_t)row0 * DIM + t * 32;
        const float* wp = W + (size_t)col0 * DIM + t * 32;
        unsigned ad = asb + s * 128 * PS * 4;
        unsigned wd = wsb + s * 128 * PS * 4;
        #pragma unroll
        for (int i = tid; i < 1024; i += 256) {
            int r = i >> 3, c = i & 7;
            cp16(ad + r * PS * 4 + c * 16, ap + (size_t)r * DIM + c * 4);
            cp16(wd + r * PS * 4 + c * 16, wp + (size_t)r * DIM + c * 4);
        }
        cp_commit();
    };

    issue(0, 0);
    issue(1, 1);
    cp_wait1();
    __syncthreads();

    float acc[2][8][4];
    #pragma unroll
    for (int mt = 0; mt < 2; mt++)
        #pragma unroll
        for (int nt = 0; nt < 8; nt++)
            #pragma unroll
            for (int i = 0; i < 4; i++) acc[mt][nt][i] = 0.f;

    for (int it = 0; it < 32; it++) {
        const float* as = As + (it & 1) * 128 * PS;
        const float* ws = Ws + (it & 1) * 128 * PS;
        #pragma unroll
        for (int kk = 0; kk < 4; kk++) {
            unsigned a[2][4];
            const int c = kk * 8 + tig;
            #pragma unroll
            for (int mt = 0; mt < 2; mt++) {
                int r = wrow * 32 + mt * 16 + gid;
                a[mt][0] = fu(as[r * PS + c]);
                a[mt][1] = fu(as[(r + 8) * PS + c]);
                a[mt][2] = fu(as[r * PS + c + 4]);
                a[mt][3] = fu(as[(r + 8) * PS + c + 4]);
            }
            #pragma unroll
            for (int nt = 0; nt < 8; nt++) {
                int n = wcol * 64 + nt * 8 + gid;
                unsigned b0 = fu(ws[n * PS + c]), b1 = fu(ws[n * PS + c + 4]);
                mma_tf32(acc[0][nt], a[0][0], a[0][1], a[0][2], a[0][3], b0, b1);
                mma_tf32(acc[1][nt], a[1][0], a[1][1], a[1][2], a[1][3], b0, b1);
            }
        }
        __syncthreads();
        if (it + 2 < 32) { issue(it + 2, it & 1); cp_wait1(); }
        else cp_wait0();
        __syncthreads();
    }

    #pragma unroll
    for (int mt = 0; mt < 2; mt++) {
        #pragma unroll
        for (int nt = 0; nt < 8; nt++) {
            int m = row0 + wrow * 32 + mt * 16 + gid;
            int n = col0 + wcol * 64 + nt * 8 + tig * 2;
            float b0 = bias[n], b1 = bias[n + 1];
            float v0 = acc[mt][nt][0] + b0;
            float v1 = acc[mt][nt][1] + b1;
            float v2 = acc[mt][nt][2] + b0;
            float v3 = acc[mt][nt][3] + b1;
            if (z == 2) {
                int bb = m >> 11, s = m & (SEQ - 1);
                int h = n >> 6, d = n & 63;
                size_t base = ((size_t)(bb * HEADS + h) * HEAD_DIM + d) * SEQ;
                g_vt[base + s]           = __float2half(v0);
                g_vt[base + SEQ + s]     = __float2half(v1);
                g_vt[base + s + 8]       = __float2half(v2);
                g_vt[base + SEQ + s + 8] = __float2half(v3);
            } else {
                v0 = rndf(v0); v1 = rndf(v1); v2 = rndf(v2); v3 = rndf(v3);
                if (z == 0) {
                    v0 = rndf(v0 * QSCL); v1 = rndf(v1 * QSCL);
                    v2 = rndf(v2 * QSCL); v3 = rndf(v3 * QSCL);
                }
                C[(size_t)m * DIM + n]           = v0;
                C[(size_t)m * DIM + n + 1]       = v1;
                C[(size_t)(m + 8) * DIM + n]     = v2;
                C[(size_t)(m + 8) * DIM + n + 1] = v3;
                Ch[(size_t)m * DIM + n]           = __float2half(v0);
                Ch[(size_t)m * DIM + n + 1]       = __float2half(v1);
                Ch[(size_t)(m + 8) * DIM + n]     = __float2half(v2);
                Ch[(size_t)(m + 8) * DIM + n + 1] = __float2half(v3);
            }
        }
    }
}

// Output-projection body (final result, no rounding).
__device__ __forceinline__ void proj_out_body(
    float* smem, const float* __restrict__ A, const float* __restrict__ W,
    const float* __restrict__ bias, float* __restrict__ C, int bx, int by) {
    float* As = smem;
    float* Ws = smem + 2 * 128 * PS;

    const int tid = threadIdx.x;
    const int wid = tid >> 5, lane = tid & 31;
    const int gid = lane >> 2, tig = lane & 3;
    const int wrow = wid & 3, wcol = wid >> 2;
    const int row0 = by * 128;
    const int col0 = bx * 128;

    const unsigned asb = sptr(As), wsb = sptr(Ws);

    auto issue = [&](int t, int s) {
        const float* ap = A + (size_t)row0 * DIM + t * 32;
        const float* wp = W + (size_t)col0 * DIM + t * 32;
        unsigned ad = asb + s * 128 * PS * 4;
        unsigned wd = wsb + s * 128 * PS * 4;
        #pragma unroll
        for (int i = tid; i < 1024; i += 256) {
            int r = i >> 3, c = i & 7;
            cp16(ad + r * PS * 4 + c * 16, ap + (size_t)r * DIM + c * 4);
            cp16(wd + r * PS * 4 + c * 16, wp + (size_t)r * DIM + c * 4);
        }
        cp_commit();
    };

    issue(0, 0);
    issue(1, 1);
    cp_wait1();
    __syncthreads();

    float acc[2][8][4];
    #pragma unroll
    for (int mt = 0; mt < 2; mt++)
        #pragma unroll
        for (int nt = 0; nt < 8; nt++)
            #pragma unroll
            for (int i = 0; i < 4; i++) acc[mt][nt][i] = 0.f;

    for (int it = 0; it < 32; it++) {
        const float* as = As + (it & 1) * 128 * PS;
        const float* ws = Ws + (it & 1) * 128 * PS;
        #pragma unroll
        for (int kk = 0; kk < 4; kk++) {
            unsigned a[2][4];
            const int c = kk * 8 + tig;
            #pragma unroll
            for (int mt = 0; mt < 2; mt++) {
                int r = wrow * 32 + mt * 16 + gid;
                a[mt][0] = fu(as[r * PS + c]);
                a[mt][1] = fu(as[(r + 8) * PS + c]);
                a[mt][2] = fu(as[r * PS + c + 4]);
                a[mt][3] = fu(as[(r + 8) * PS + c + 4]);
            }
            #pragma unroll
            for (int nt = 0; nt < 8; nt++) {
                int n = wcol * 64 + nt * 8 + gid;
                unsigned b0 = fu(ws[n * PS + c]), b1 = fu(ws[n * PS + c + 4]);
                mma_tf32(acc[0][nt], a[0][0], a[0][1], a[0][2], a[0][3], b0, b1);
                mma_tf32(acc[1][nt], a[1][0], a[1][1], a[1][2], a[1][3], b0, b1);
            }
        }
        __syncthreads();
        if (it + 2 < 32) { issue(it + 2, it & 1); cp_wait1(); }
        else cp_wait0();
        __syncthreads();
    }

    #pragma unroll
    for (int mt = 0; mt < 2; mt++) {
        #pragma unroll
        for (int nt = 0; nt < 8; nt++) {
            int m = row0 + wrow * 32 + mt * 16 + gid;
            int n = col0 + wcol * 64 + nt * 8 + tig * 2;
            float b0 = bias[n], b1 = bias[n + 1];
            C[(size_t)m * DIM + n]           = acc[mt][nt][0] + b0;
            C[(size_t)m * DIM + n + 1]       = acc[mt][nt][1] + b1;
            C[(size_t)(m + 8) * DIM + n]     = acc[mt][nt][2] + b0;
            C[(size_t)(m + 8) * DIM + n + 1] = acc[mt][nt][3] + b1;
        }
    }
}

// ================= fused flash attention: tf32 QK, fp16 PV (no shuffles) =========
#define KQS 68    // floats per K/Q smem row
#define VTS 72    // halves per Vt smem row
__global__ __launch_bounds__(256, 2) void flash_kernel() {
    extern __shared__ float smem[];
    float* Qs = smem;                                   // [128][68] f32
    float* Ks = Qs + 128 * KQS;                         // 2 x [64][68] f32
    __half* Vt = (__half*)(Ks + 2 * 64 * KQS);          // 2 x [64][72] fp16

    const int tid = threadIdx.x;
    const int wid = tid >> 5, lane = tid & 31;
    const int gid = lane >> 2, tig = lane & 3;
    const int q0 = blockIdx.x * 128;
    const int bh = blockIdx.y;
    const int b = bh / HEADS, h = bh % HEADS;

    const float* qbase = g_q + ((size_t)b * SEQ + q0) * DIM + h * HEAD_DIM;
    const float* kbase = g_k + (size_t)b * SEQ * DIM + h * HEAD_DIM;
    const __half* vtbase = g_vt + (size_t)bh * HEAD_DIM * SEQ;

    const unsigned qsb = sptr(Qs), ksb = sptr(Ks), vsb = sptr(Vt);

    auto issue_kv = [&](int kt, int s) {
        const float* kp = kbase + (size_t)kt * 64 * DIM;
        unsigned kd = ksb + s * 64 * KQS * 4;
        #pragma unroll
        for (int i = tid; i < 1024; i += 256) {
            int r = i >> 4, c = i & 15;
            cp16(kd + r * KQS * 4 + c * 16, kp + (size_t)r * DIM + c * 4);
        }
        const __half* vp = vtbase + kt * 64;
        unsigned vd = vsb + s * 64 * VTS * 2;
        #pragma unroll
        for (int i = tid; i < 512; i += 256) {
            int r = i >> 3, c = i & 7;
            cp16(vd + r * VTS * 2 + c * 16, vp + (size_t)r * SEQ + c * 8);
        }
        cp_commit();
    };

    #pragma unroll
    for (int i = tid; i < 2048; i += 256) {
        int r = i >> 4, c = i & 15;
        cp16(qsb + r * KQS * 4 + c * 16, qbase + (size_t)r * DIM + c * 4);
    }
    issue_kv(0, 0);
    issue_kv(1, 1);
    cp_wait1();
    __syncthreads();

    unsigned qa[8][4];
    {
        int r = wid * 16 + gid;
        #pragma unroll
        for (int kk = 0; kk < 8; kk++) {
            int c = kk * 8 + tig;
            qa[kk][0] = fu(Qs[r * KQS + c]);
            qa[kk][1] = fu(Qs[(r + 8) * KQS + c]);
            qa[kk][2] = fu(Qs[r * KQS + c + 4]);
            qa[kk][3] = fu(Qs[(r + 8) * KQS + c + 4]);
        }
    }

    float oacc[8][4];
    #pragma unroll
    for (int nt = 0; nt < 8; nt++)
        #pragma unroll
        for (int i = 0; i < 4; i++) oacc[nt][i] = 0.f;
    float l0 = 0.f, l1 = 0.f;

    const int rowq = q0 + wid * 16 + gid;

    for (int kt = 0; kt < SEQ / 64; kt++) {
        const float* ks = Ks + (kt & 1) * 64 * KQS;
        const __half* vs = Vt + (kt & 1) * 64 * VTS;

        float sacc[8][4];
        #pragma unroll
        for (int nt = 0; nt < 8; nt++)
            #pragma unroll
            for (int i = 0; i < 4; i++) sacc[nt][i] = 0.f;
        #pragma unroll
        for (int kk = 0; kk < 8; kk++) {
            #pragma unroll
            for (int nt = 0; nt < 8; nt++) {
                unsigned b0 = fu(ks[(nt * 8 + gid) * KQS + kk * 8 + tig]);
                unsigned b1 = fu(ks[(nt * 8 + gid) * KQS + kk * 8 + tig + 4]);
                mma_tf32(sacc[nt], qa[kk][0], qa[kk][1], qa[kk][2], qa[kk][3], b0, b1);
            }
        }

        // ---- 2^s, denominators, pack P to f16x2 (A-fragment layout) ----
        unsigned pa0[8], pa1[8];
        #pragma unroll
        for (int nt = 0; nt < 8; nt++) {
            float p0 = ex2(sacc[nt][0]);
            float p1 = ex2(sacc[nt][1]);
            float p2 = ex2(sacc[nt][2]);
            float p3 = ex2(sacc[nt][3]);
            l0 += p0 + p1;  l1 += p2 + p3;
            pa0[nt] = packh(p1, p0);
            pa1[nt] = packh(p3, p2);
        }

        // ---- O += P * V via f16 m16n8k16 (no shuffles) ----
        #pragma unroll
        for (int j = 0; j < 4; j++) {
            unsigned a0 = pa0[2 * j],     a1 = pa1[2 * j];
            unsigned a2 = pa0[2 * j + 1], a3 = pa1[2 * j + 1];
            #pragma unroll
            for (int nt = 0; nt < 8; nt++) {
                const __half* vrow = vs + (nt * 8 + gid) * VTS + j * 16 + tig * 2;
                unsigned b0 = *(const unsigned*)vrow;
                unsigned b1 = *(const unsigned*)(vrow + 8);
                mma_f16(oacc[nt], a0, a1, a2, a3, b0, b1);
            }
        }

        __syncthreads();
        if (kt + 2 < SEQ / 64) { issue_kv(kt + 2, kt & 1); cp_wait1(); }
        else cp_wait0();
        __syncthreads();
    }

    l0 += __shfl_xor_sync(~0u, l0, 1);
    l0 += __shfl_xor_sync(~0u, l0, 2);
    l1 += __shfl_xor_sync(~0u, l1, 1);
    l1 += __shfl_xor_sync(~0u, l1, 2);

    const float il0 = 1.f / l0, il1 = 1.f / l1;
    float* orow = g_ho + ((size_t)b * SEQ + rowq) * DIM + h * HEAD_DIM;
    #pragma unroll
    for (int nt = 0; nt < 8; nt++) {
        orow[nt * 8 + 2 * tig]               = rndf(oacc[nt][0] * il0);
        orow[nt * 8 + 2 * tig + 1]           = rndf(oacc[nt][1] * il0);
        orow[8 * DIM + nt * 8 + 2 * tig]     = rndf(oacc[nt][2] * il1);
        orow[8 * DIM + nt * 8 + 2 * tig + 1] = rndf(oacc[nt][3] * il1);
    }
    if (tig == 0) {
        size_t mi = (size_t)bh * SEQ + rowq;
        g_l[mi] = l0;
        g_l[mi + 8] = l1;
    }
}

// ================= head-mean body (fp16 QK recompute, m16n8k16) ==================
#define QHS 72    // halves per Q/K smem row
__device__ __forceinline__ void mean_body(float* smem_f, float* __restrict__ amean,
                                          int bkx, int bqy, int b) {
    __half* Qh = (__half*)smem_f;        // 2 x [128][72]
    __half* Kh = Qh + 2 * 128 * QHS;     // 2 x [64][72]

    const int tid = threadIdx.x;
    const int wid = tid >> 5, lane = tid & 31;
    const int gid = lane >> 2, tig = lane & 3;
    const int k0 = bkx * 64;
    const int q0 = bqy * 128;

    const __half* qbase = g_qh + ((size_t)b * SEQ + q0) * DIM;
    const __half* kbase = g_kh + ((size_t)b * SEQ + k0) * DIM;

    const unsigned qsb = sptr(Qh), ksb = sptr(Kh);

    auto issue_h = [&](int h, int s) {
        const __half* qp = qbase + h * HEAD_DIM;
        const __half* kp = kbase + h * HEAD_DIM;
        unsigned qd = qsb + s * 128 * QHS * 2;
        unsigned kd = ksb + s * 64 * QHS * 2;
        #pragma unroll
        for (int i = tid; i < 1024; i += 256) {
            int r = i >> 3, c = i & 7;
            cp16(qd + r * QHS * 2 + c * 16, qp + (size_t)r * DIM + c * 8);
        }
        #pragma unroll
        for (int i = tid; i < 512; i += 256) {
            int r = i >> 3, c = i & 7;
            cp16(kd + r * QHS * 2 + c * 16, kp + (size_t)r * DIM + c * 8);
        }
        cp_commit();
    };

    issue_h(0, 0);
    issue_h(1, 1);
    cp_wait1();
    __syncthreads();

    float amacc[8][4];
    #pragma unroll
    for (int nt = 0; nt < 8; nt++)
        #pragma unroll
        for (int i = 0; i < 4; i++) amacc[nt][i] = 0.f;

    for (int h = 0; h < HEADS; h++) {
        const __half* qs = Qh + (h & 1) * 128 * QHS;
        const __half* ks = Kh + (h & 1) * 64 * QHS;

        const int r = wid * 16 + gid;

        float sacc[8][4];
        #pragma unroll
        for (int nt = 0; nt < 8; nt++)
            #pragma unroll
            for (int i = 0; i < 4; i++) sacc[nt][i] = 0.f;

        #pragma unroll
        for (int j = 0; j < 4; j++) {
            unsigned a0 = *(const unsigned*)&qs[r * QHS + j * 16 + tig * 2];
            unsigned a1 = *(const unsigned*)&qs[(r + 8) * QHS + j * 16 + tig * 2];
            unsigned a2 = *(const unsigned*)&qs[r * QHS + j * 16 + 8 + tig * 2];
            unsigned a3 = *(const unsigned*)&qs[(r + 8) * QHS + j * 16 + 8 + tig * 2];
            #pragma unroll
            for (int nt = 0; nt < 8; nt++) {
                const __half* krow = ks + (nt * 8 + gid) * QHS + j * 16 + tig * 2;
                unsigned b0 = *(const unsigned*)krow;
                unsigned b1 = *(const unsigned*)(krow + 8);
                mma_f16(sacc[nt], a0, a1, a2, a3, b0, b1);
            }
        }

        size_t mi = ((size_t)(b * HEADS + h)) * SEQ + q0 + wid * 16 + gid;
        float c0 = -lg2(g_l[mi]) - 4.0f;
        float c1 = -lg2(g_l[mi + 8]) - 4.0f;
        #pragma unroll
        for (int nt = 0; nt < 8; nt++) {
            amacc[nt][0] += ex2(sacc[nt][0] + c0);
            amacc[nt][1] += ex2(sacc[nt][1] + c0);
            amacc[nt][2] += ex2(sacc[nt][2] + c1);
            amacc[nt][3] += ex2(sacc[nt][3] + c1);
        }

        __syncthreads();
        if (h + 2 < HEADS) { issue_h(h + 2, h & 1); cp_wait1(); }
        else cp_wait0();
        __syncthreads();
    }

    const int row = q0 + wid * 16 + gid;
    float* arow = amean + ((size_t)b * SEQ + row) * SEQ + k0;
    #pragma unroll
    for (int nt = 0; nt < 8; nt++) {
        arow[nt * 8 + 2 * tig]               = amacc[nt][0];
        arow[nt * 8 + 2 * tig + 1]           = amacc[nt][1];
        arow[8 * SEQ + nt * 8 + 2 * tig]     = amacc[nt][2];
        arow[8 * SEQ + nt * 8 + 2 * tig + 1] = amacc[nt][3];
    }
}

// ================= tail: proj_out (256 blocks) + mean (1024 blocks) ==============
__global__ __launch_bounds__(256, 2) void tail_kernel(
    float* __restrict__ amean, const float* __restrict__ A,
    const float* __restrict__ W, const float* __restrict__ bias,
    float* __restrict__ C) {
    extern __shared__ float smem[];
    if (blockIdx.x < 256) {
        proj_out_body(smem, A, W, bias, C, blockIdx.x & 7, blockIdx.x >> 3);
    } else {
        int bx = blockIdx.x - 256;
        mean_body(smem, amean, bx & 31, (bx >> 5) & 15, bx >> 9);
    }
}

// ---------------- launch ------------------------------------------------------------
#define PROJ_SMEM (4 * 128 * PS * 4)
#define FLASH_SMEM ((128 * KQS + 2 * 64 * KQS) * 4 + 2 * 64 * VTS * 2)
#define MEAN_SMEM ((2 * 128 * QHS + 2 * 64 * QHS) * 2)
#define TAIL_SMEM (MEAN_SMEM > PROJ_SMEM ? MEAN_SMEM : PROJ_SMEM)

extern "C" void kernel_launch(void* const* d_in, const int* in_sizes, int n_in,
                              void* d_out, int out_size) {
    const float* x  = (const float*)d_in[0];
    const float* wq = (const float*)d_in[1];
    const float* bq = (const float*)d_in[2];
    const float* wk = (const float*)d_in[3];
    const float* bk = (const float*)d_in[4];
    const float* wv = (const float*)d_in[5];
    const float* bv = (const float*)d_in[6];
    const float* wo = (const float*)d_in[7];
    const float* bo = (const float*)d_in[8];

    float* out_o    = (float*)d_out;
    float* out_mean = out_o + (size_t)BS * DIM;

    static float* p_x = nullptr;
    static float* p_wo = nullptr;
    static float* p_ho = nullptr;
    if (!p_x) {
        cudaGetSymbolAddress((void**)&p_x, g_x);
        cudaGetSymbolAddress((void**)&p_wo, g_wo);
        cudaGetSymbolAddress((void**)&p_ho, g_ho);
        cudaFuncSetAttribute(proj_qkv,
                             cudaFuncAttributeMaxDynamicSharedMemorySize, PROJ_SMEM);
        cudaFuncSetAttribute(flash_kernel,
                             cudaFuncAttributeMaxDynamicSharedMemorySize, FLASH_SMEM);
        cudaFuncSetAttribute(tail_kernel,
                             cudaFuncAttributeMaxDynamicSharedMemorySize, TAIL_SMEM);
    }

    round_all<<<(NTOT4 + 255) / 256, 256>>>(x, wq, wk, wv, wo);

    proj_qkv<<<dim3(DIM / 128, BS / 128, 3), 256, PROJ_SMEM>>>(p_x, bq, bk, bv);

    flash_kernel<<<dim3(SEQ / 128, BATCH * HEADS), 256, FLASH_SMEM>>>();

    tail_kernel<<<256 + SEQ / 64 * (SEQ / 128) * BATCH, 256, TAIL_SMEM>>>(
        out_mean, p_ho, p_wo, bo, out_o);
}

// round 14
// speedup vs baseline: 1.5136x; 1.1313x over previous
#include <cuda_runtime.h>
#include <cuda_fp16.h>
#include <math.h>

#define BATCH 2
#define SEQ 2048
#define DIM 1024
#define HEADS 16
#define HEAD_DIM 64
#define BS (BATCH * SEQ)
#define QSCL 0.18033688011112042f   // 0.125 * log2(e)

// ---------------- scratch (static device memory; no allocations) ----------------
__device__ float g_x[BS * DIM];
__device__ float g_wq[DIM * DIM];
__device__ float g_wk[DIM * DIM];
__device__ float g_wv[DIM * DIM];
__device__ float g_wo[DIM * DIM];
__device__ __half g_qh[BS * DIM];          // fp16 q, log2 domain (pre-scaled)
__device__ __half g_kh[BS * DIM];          // fp16 k
__device__ __half g_vt[(size_t)BATCH * HEADS * HEAD_DIM * SEQ];  // V^T fp16
__device__ float g_ho[BS * DIM];
__device__ float g_l[BATCH * HEADS * SEQ];

// ---------------- helpers --------------------------------------------------------
__device__ __forceinline__ unsigned f2tf(float f) {
    unsigned r;
    asm("cvt.rna.tf32.f32 %0, %1;" : "=r"(r) : "f"(f));
    return r;
}
__device__ __forceinline__ float rndf(float f) { return __uint_as_float(f2tf(f)); }
__device__ __forceinline__ float ex2(float x) {
    float r; asm("ex2.approx.ftz.f32 %0, %1;" : "=f"(r) : "f"(x)); return r;
}
__device__ __forceinline__ float lg2(float x) {
    float r; asm("lg2.approx.ftz.f32 %0, %1;" : "=f"(r) : "f"(x)); return r;
}
__device__ __forceinline__ unsigned packh(float hi, float lo) {
    unsigned r;
    asm("cvt.rn.f16x2.f32 %0, %1, %2;" : "=r"(r) : "f"(hi), "f"(lo));
    return r;
}

__device__ __forceinline__ void mma_tf32(float c[4], unsigned a0, unsigned a1,
                                         unsigned a2, unsigned a3,
                                         unsigned b0, unsigned b1) {
    asm volatile(
        "mma.sync.aligned.m16n8k8.row.col.f32.tf32.tf32.f32 "
        "{%0,%1,%2,%3}, {%4,%5,%6,%7}, {%8,%9}, {%0,%1,%2,%3};"
        : "+f"(c[0]), "+f"(c[1]), "+f"(c[2]), "+f"(c[3])
        : "r"(a0), "r"(a1), "r"(a2), "r"(a3), "r"(b0), "r"(b1));
}

__device__ __forceinline__ void mma_f16(float c[4], unsigned a0, unsigned a1,
                                        unsigned a2, unsigned a3,
                                        unsigned b0, unsigned b1) {
    asm volatile(
        "mma.sync.aligned.m16n8k16.row.col.f32.f16.f16.f32 "
        "{%0,%1,%2,%3}, {%4,%5,%6,%7}, {%8,%9}, {%0,%1,%2,%3};"
        : "+f"(c[0]), "+f"(c[1]), "+f"(c[2]), "+f"(c[3])
        : "r"(a0), "r"(a1), "r"(a2), "r"(a3), "r"(b0), "r"(b1));
}

__device__ __forceinline__ void cp16(unsigned dst, const void* src) {
    asm volatile("cp.async.cg.shared.global [%0], [%1], 16;" :: "r"(dst), "l"(src));
}
__device__ __forceinline__ void cp_commit() {
    asm volatile("cp.async.commit_group;" ::: "memory");
}
__device__ __forceinline__ void cp_wait1() {
    asm volatile("cp.async.wait_group 1;" ::: "memory");
}
__device__ __forceinline__ void cp_wait0() {
    asm volatile("cp.async.wait_group 0;" ::: "memory");
}
__device__ __forceinline__ unsigned sptr(const void* p) {
    return (unsigned)__cvta_generic_to_shared(p);
}
__device__ __forceinline__ unsigned fu(float f) { return __float_as_uint(f); }

// ================= prepass: RN-round all 5 tensors in one launch =================
#define NX4 (BS * DIM / 4)
#define NW4 (DIM * DIM / 4)
#define NTOT4 (NX4 + 4 * NW4)

__global__ __launch_bounds__(256) void round_all(
    const float* __restrict__ x,  const float* __restrict__ wq,
    const float* __restrict__ wk, const float* __restrict__ wv,
    const float* __restrict__ wo) {
    int i = blockIdx.x * 256 + threadIdx.x;
    if (i >= NTOT4) return;
    const float* src; float* dst; int off;
    if (i < NX4) { src = x; dst = g_x; off = i; }
    else {
        int j = i - NX4, w = j >> 18;
        off = j & (NW4 - 1);
        if (w == 0)      { src = wq; dst = g_wq; }
        else if (w == 1) { src = wk; dst = g_wk; }
        else if (w == 2) { src = wv; dst = g_wv; }
        else             { src = wo; dst = g_wo; }
    }
    float4 v = ((const float4*)src)[off];
    v.x = rndf(v.x); v.y = rndf(v.y); v.z = rndf(v.z); v.w = rndf(v.w);
    ((float4*)dst)[off] = v;
}

// ================= GEMM bodies ===================================================
#define PS 36

// QKV fused projection. z==0: Q -> g_qh (scaled, log2, fp16). z==1: K -> g_kh.
// z==2: V -> g_vt fp16 transposed.
__global__ __launch_bounds__(256, 2) void proj_qkv(
    const float* __restrict__ A,
    const float* __restrict__ bq, const float* __restrict__ bk,
    const float* __restrict__ bv) {
    extern __shared__ float smem[];
    float* As = smem;
    float* Ws = smem + 2 * 128 * PS;

    const int z = blockIdx.z;
    const float* W; const float* bias; __half* Ch;
    if (z == 0)      { W = g_wq; bias = bq; Ch = g_qh; }
    else if (z == 1) { W = g_wk; bias = bk; Ch = g_kh; }
    else             { W = g_wv; bias = bv; Ch = nullptr; }

    const int tid = threadIdx.x;
    const int wid = tid >> 5, lane = tid & 31;
    const int gid = lane >> 2, tig = lane & 3;
    const int wrow = wid & 3, wcol = wid >> 2;
    const int row0 = blockIdx.y * 128;
    const int col0 = blockIdx.x * 128;

    const unsigned asb = sptr(As), wsb = sptr(Ws);

    auto issue = [&](int t, int s) {
        const float* ap = A + (size_t)row0 * DIM + t * 32;
        const float* wp = W + (size_t)col0 * DIM + t * 32;
        unsigned ad = asb + s * 128 * PS * 4;
        unsigned wd = wsb + s * 128 * PS * 4;
        #pragma unroll
        for (int i = tid; i < 1024; i += 256) {
            int r = i >> 3, c = i & 7;
            cp16(ad + r * PS * 4 + c * 16, ap + (size_t)r * DIM + c * 4);
            cp16(wd + r * PS * 4 + c * 16, wp + (size_t)r * DIM + c * 4);
        }
        cp_commit();
    };

    issue(0, 0);
    issue(1, 1);
    cp_wait1();
    __syncthreads();

    float acc[2][8][4];
    #pragma unroll
    for (int mt = 0; mt < 2; mt++)
        #pragma unroll
        for (int nt = 0; nt < 8; nt++)
            #pragma unroll
            for (int i = 0; i < 4; i++) acc[mt][nt][i] = 0.f;

    for (int it = 0; it < 32; it++) {
        const float* as = As + (it & 1) * 128 * PS;
        const float* ws = Ws + (it & 1) * 128 * PS;
        #pragma unroll
        for (int kk = 0; kk < 4; kk++) {
            unsigned a[2][4];
            const int c = kk * 8 + tig;
            #pragma unroll
            for (int mt = 0; mt < 2; mt++) {
                int r = wrow * 32 + mt * 16 + gid;
                a[mt][0] = fu(as[r * PS + c]);
                a[mt][1] = fu(as[(r + 8) * PS + c]);
                a[mt][2] = fu(as[r * PS + c + 4]);
                a[mt][3] = fu(as[(r + 8) * PS + c + 4]);
            }
            #pragma unroll
            for (int nt = 0; nt < 8; nt++) {
                int n = wcol * 64 + nt * 8 + gid;
                unsigned b0 = fu(ws[n * PS + c]), b1 = fu(ws[n * PS + c + 4]);
                mma_tf32(acc[0][nt], a[0][0], a[0][1], a[0][2], a[0][3], b0, b1);
                mma_tf32(acc[1][nt], a[1][0], a[1][1], a[1][2], a[1][3], b0, b1);
            }
        }
        __syncthreads();
        if (it + 2 < 32) { issue(it + 2, it & 1); cp_wait1(); }
        else cp_wait0();
        __syncthreads();
    }

    #pragma unroll
    for (int mt = 0; mt < 2; mt++) {
        #pragma unroll
        for (int nt = 0; nt < 8; nt++) {
            int m = row0 + wrow * 32 + mt * 16 + gid;
            int n = col0 + wcol * 64 + nt * 8 + tig * 2;
            float b0 = bias[n], b1 = bias[n + 1];
            float v0 = acc[mt][nt][0] + b0;
            float v1 = acc[mt][nt][1] + b1;
            float v2 = acc[mt][nt][2] + b0;
            float v3 = acc[mt][nt][3] + b1;
            if (z == 2) {
                int bb = m >> 11, s = m & (SEQ - 1);
                int h = n >> 6, d = n & 63;
                size_t base = ((size_t)(bb * HEADS + h) * HEAD_DIM + d) * SEQ;
                g_vt[base + s]           = __float2half(v0);
                g_vt[base + SEQ + s]     = __float2half(v1);
                g_vt[base + s + 8]       = __float2half(v2);
                g_vt[base + SEQ + s + 8] = __float2half(v3);
            } else {
                if (z == 0) { v0 *= QSCL; v1 *= QSCL; v2 *= QSCL; v3 *= QSCL; }
                Ch[(size_t)m * DIM + n]           = __float2half(v0);
                Ch[(size_t)m * DIM + n + 1]       = __float2half(v1);
                Ch[(size_t)(m + 8) * DIM + n]     = __float2half(v2);
                Ch[(size_t)(m + 8) * DIM + n + 1] = __float2half(v3);
            }
        }
    }
}

// Output-projection body (final result, no rounding).
__device__ __forceinline__ void proj_out_body(
    float* smem, const float* __restrict__ A, const float* __restrict__ W,
    const float* __restrict__ bias, float* __restrict__ C, int bx, int by) {
    float* As = smem;
    float* Ws = smem + 2 * 128 * PS;

    const int tid = threadIdx.x;
    const int wid = tid >> 5, lane = tid & 31;
    const int gid = lane >> 2, tig = lane & 3;
    const int wrow = wid & 3, wcol = wid >> 2;
    const int row0 = by * 128;
    const int col0 = bx * 128;

    const unsigned asb = sptr(As), wsb = sptr(Ws);

    auto issue = [&](int t, int s) {
        const float* ap = A + (size_t)row0 * DIM + t * 32;
        const float* wp = W + (size_t)col0 * DIM + t * 32;
        unsigned ad = asb + s * 128 * PS * 4;
        unsigned wd = wsb + s * 128 * PS * 4;
        #pragma unroll
        for (int i = tid; i < 1024; i += 256) {
            int r = i >> 3, c = i & 7;
            cp16(ad + r * PS * 4 + c * 16, ap + (size_t)r * DIM + c * 4);
            cp16(wd + r * PS * 4 + c * 16, wp + (size_t)r * DIM + c * 4);
        }
        cp_commit();
    };

    issue(0, 0);
    issue(1, 1);
    cp_wait1();
    __syncthreads();

    float acc[2][8][4];
    #pragma unroll
    for (int mt = 0; mt < 2; mt++)
        #pragma unroll
        for (int nt = 0; nt < 8; nt++)
            #pragma unroll
            for (int i = 0; i < 4; i++) acc[mt][nt][i] = 0.f;

    for (int it = 0; it < 32; it++) {
        const float* as = As + (it & 1) * 128 * PS;
        const float* ws = Ws + (it & 1) * 128 * PS;
        #pragma unroll
        for (int kk = 0; kk < 4; kk++) {
            unsigned a[2][4];
            const int c = kk * 8 + tig;
            #pragma unroll
            for (int mt = 0; mt < 2; mt++) {
                int r = wrow * 32 + mt * 16 + gid;
                a[mt][0] = fu(as[r * PS + c]);
                a[mt][1] = fu(as[(r + 8) * PS + c]);
                a[mt][2] = fu(as[r * PS + c + 4]);
                a[mt][3] = fu(as[(r + 8) * PS + c + 4]);
            }
            #pragma unroll
            for (int nt = 0; nt < 8; nt++) {
                int n = wcol * 64 + nt * 8 + gid;
                unsigned b0 = fu(ws[n * PS + c]), b1 = fu(ws[n * PS + c + 4]);
                mma_tf32(acc[0][nt], a[0][0], a[0][1], a[0][2], a[0][3], b0, b1);
                mma_tf32(acc[1][nt], a[1][0], a[1][1], a[1][2], a[1][3], b0, b1);
            }
        }
        __syncthreads();
        if (it + 2 < 32) { issue(it + 2, it & 1); cp_wait1(); }
        else cp_wait0();
        __syncthreads();
    }

    #pragma unroll
    for (int mt = 0; mt < 2; mt++) {
        #pragma unroll
        for (int nt = 0; nt < 8; nt++) {
            int m = row0 + wrow * 32 + mt * 16 + gid;
            int n = col0 + wcol * 64 + nt * 8 + tig * 2;
            float b0 = bias[n], b1 = bias[n + 1];
            C[(size_t)m * DIM + n]           = acc[mt][nt][0] + b0;
            C[(size_t)m * DIM + n + 1]       = acc[mt][nt][1] + b1;
            C[(size_t)(m + 8) * DIM + n]     = acc[mt][nt][2] + b0;
            C[(size_t)(m + 8) * DIM + n + 1] = acc[mt][nt][3] + b1;
        }
    }
}

// ================= fused flash attention: fp16 QK + fp16 PV ======================
#define QHS 72    // halves per smem row (Q/K/Vt)
__global__ __launch_bounds__(256, 2) void flash_kernel() {
    extern __shared__ __half smem_h[];
    __half* Qs = smem_h;                    // [128][72]
    __half* Ks = Qs + 128 * QHS;            // 2 x [64][72]
    __half* Vt = Ks + 2 * 64 * QHS;         // 2 x [64][72]

    const int tid = threadIdx.x;
    const int wid = tid >> 5, lane = tid & 31;
    const int gid = lane >> 2, tig = lane & 3;
    const int q0 = blockIdx.x * 128;
    const int bh = blockIdx.y;
    const int b = bh / HEADS, h = bh % HEADS;

    const __half* qbase = g_qh + ((size_t)b * SEQ + q0) * DIM + h * HEAD_DIM;
    const __half* kbase = g_kh + (size_t)b * SEQ * DIM + h * HEAD_DIM;
    const __half* vtbase = g_vt + (size_t)bh * HEAD_DIM * SEQ;

    const unsigned qsb = sptr(Qs), ksb = sptr(Ks), vsb = sptr(Vt);

    auto issue_kv = [&](int kt, int s) {
        const __half* kp = kbase + (size_t)kt * 64 * DIM;
        unsigned kd = ksb + s * 64 * QHS * 2;
        #pragma unroll
        for (int i = tid; i < 512; i += 256) {
            int r = i >> 3, c = i & 7;
            cp16(kd + r * QHS * 2 + c * 16, kp + (size_t)r * DIM + c * 8);
        }
        const __half* vp = vtbase + kt * 64;
        unsigned vd = vsb + s * 64 * QHS * 2;
        #pragma unroll
        for (int i = tid; i < 512; i += 256) {
            int r = i >> 3, c = i & 7;
            cp16(vd + r * QHS * 2 + c * 16, vp + (size_t)r * SEQ + c * 8);
        }
        cp_commit();
    };

    #pragma unroll
    for (int i = tid; i < 1024; i += 256) {
        int r = i >> 3, c = i & 7;
        cp16(qsb + r * QHS * 2 + c * 16, qbase + (size_t)r * DIM + c * 8);
    }
    issue_kv(0, 0);
    issue_kv(1, 1);
    cp_wait1();
    __syncthreads();

    // preload Q fragments: 4 k-steps x 4 regs
    unsigned qa[4][4];
    {
        int r = wid * 16 + gid;
        #pragma unroll
        for (int j = 0; j < 4; j++) {
            qa[j][0] = *(const unsigned*)&Qs[r * QHS + j * 16 + tig * 2];
            qa[j][1] = *(const unsigned*)&Qs[(r + 8) * QHS + j * 16 + tig * 2];
            qa[j][2] = *(const unsigned*)&Qs[r * QHS + j * 16 + 8 + tig * 2];
            qa[j][3] = *(const unsigned*)&Qs[(r + 8) * QHS + j * 16 + 8 + tig * 2];
        }
    }

    float oacc[8][4];
    #pragma unroll
    for (int nt = 0; nt < 8; nt++)
        #pragma unroll
        for (int i = 0; i < 4; i++) oacc[nt][i] = 0.f;
    float l0 = 0.f, l1 = 0.f;

    const int rowq = q0 + wid * 16 + gid;

    for (int kt = 0; kt < SEQ / 64; kt++) {
        const __half* ks = Ks + (kt & 1) * 64 * QHS;
        const __half* vs = Vt + (kt & 1) * 64 * QHS;

        float sacc[8][4];
        #pragma unroll
        for (int nt = 0; nt < 8; nt++)
            #pragma unroll
            for (int i = 0; i < 4; i++) sacc[nt][i] = 0.f;
        #pragma unroll
        for (int j = 0; j < 4; j++) {
            #pragma unroll
            for (int nt = 0; nt < 8; nt++) {
                const __half* krow = ks + (nt * 8 + gid) * QHS + j * 16 + tig * 2;
                unsigned b0 = *(const unsigned*)krow;
                unsigned b1 = *(const unsigned*)(krow + 8);
                mma_f16(sacc[nt], qa[j][0], qa[j][1], qa[j][2], qa[j][3], b0, b1);
            }
        }

        // ---- 2^s, denominators, pack P to f16x2 (A-fragment layout) ----
        unsigned pa0[8], pa1[8];
        #pragma unroll
        for (int nt = 0; nt < 8; nt++) {
            float p0 = ex2(sacc[nt][0]);
            float p1 = ex2(sacc[nt][1]);
            float p2 = ex2(sacc[nt][2]);
            float p3 = ex2(sacc[nt][3]);
            l0 += p0 + p1;  l1 += p2 + p3;
            pa0[nt] = packh(p1, p0);
            pa1[nt] = packh(p3, p2);
        }

        // ---- O += P * V via f16 m16n8k16 (no shuffles) ----
        #pragma unroll
        for (int j = 0; j < 4; j++) {
            unsigned a0 = pa0[2 * j],     a1 = pa1[2 * j];
            unsigned a2 = pa0[2 * j + 1], a3 = pa1[2 * j + 1];
            #pragma unroll
            for (int nt = 0; nt < 8; nt++) {
                const __half* vrow = vs + (nt * 8 + gid) * QHS + j * 16 + tig * 2;
                unsigned b0 = *(const unsigned*)vrow;
                unsigned b1 = *(const unsigned*)(vrow + 8);
                mma_f16(oacc[nt], a0, a1, a2, a3, b0, b1);
            }
        }

        __syncthreads();
        if (kt + 2 < SEQ / 64) { issue_kv(kt + 2, kt & 1); cp_wait1(); }
        else cp_wait0();
        __syncthreads();
    }

    l0 += __shfl_xor_sync(~0u, l0, 1);
    l0 += __shfl_xor_sync(~0u, l0, 2);
    l1 += __shfl_xor_sync(~0u, l1, 1);
    l1 += __shfl_xor_sync(~0u, l1, 2);

    const float il0 = 1.f / l0, il1 = 1.f / l1;
    float* orow = g_ho + ((size_t)b * SEQ + rowq) * DIM + h * HEAD_DIM;
    #pragma unroll
    for (int nt = 0; nt < 8; nt++) {
        orow[nt * 8 + 2 * tig]               = rndf(oacc[nt][0] * il0);
        orow[nt * 8 + 2 * tig + 1]           = rndf(oacc[nt][1] * il0);
        orow[8 * DIM + nt * 8 + 2 * tig]     = rndf(oacc[nt][2] * il1);
        orow[8 * DIM + nt * 8 + 2 * tig + 1] = rndf(oacc[nt][3] * il1);
    }
    if (tig == 0) {
        size_t mi = (size_t)bh * SEQ + rowq;
        g_l[mi] = l0;
        g_l[mi + 8] = l1;
    }
}

// ================= head-mean body (fp16 QK recompute, m16n8k16) ==================
__device__ __forceinline__ void mean_body(float* smem_f, float* __restrict__ amean,
                                          int bkx, int bqy, int b) {
    __half* Qh = (__half*)smem_f;        // 2 x [128][72]
    __half* Kh = Qh + 2 * 128 * QHS;     // 2 x [64][72]

    const int tid = threadIdx.x;
    const int wid = tid >> 5, lane = tid & 31;
    const int gid = lane >> 2, tig = lane & 3;
    const int k0 = bkx * 64;
    const int q0 = bqy * 128;

    const __half* qbase = g_qh + ((size_t)b * SEQ + q0) * DIM;
    const __half* kbase = g_kh + ((size_t)b * SEQ + k0) * DIM;

    const unsigned qsb = sptr(Qh), ksb = sptr(Kh);

    auto issue_h = [&](int h, int s) {
        const __half* qp = qbase + h * HEAD_DIM;
        const __half* kp = kbase + h * HEAD_DIM;
        unsigned qd = qsb + s * 128 * QHS * 2;
        unsigned kd = ksb + s * 64 * QHS * 2;
        #pragma unroll
        for (int i = tid; i < 1024; i += 256) {
            int r = i >> 3, c = i & 7;
            cp16(qd + r * QHS * 2 + c * 16, qp + (size_t)r * DIM + c * 8);
        }
        #pragma unroll
        for (int i = tid; i < 512; i += 256) {
            int r = i >> 3, c = i & 7;
            cp16(kd + r * QHS * 2 + c * 16, kp + (size_t)r * DIM + c * 8);
        }
        cp_commit();
    };

    issue_h(0, 0);
    issue_h(1, 1);
    cp_wait1();
    __syncthreads();

    float amacc[8][4];
    #pragma unroll
    for (int nt = 0; nt < 8; nt++)
        #pragma unroll
        for (int i = 0; i < 4; i++) amacc[nt][i] = 0.f;

    for (int h = 0; h < HEADS; h++) {
        const __half* qs = Qh + (h & 1) * 128 * QHS;
        const __half* ks = Kh + (h & 1) * 64 * QHS;

        const int r = wid * 16 + gid;

        float sacc[8][4];
        #pragma unroll
        for (int nt = 0; nt < 8; nt++)
            #pragma unroll
            for (int i = 0; i < 4; i++) sacc[nt][i] = 0.f;

        #pragma unroll
        for (int j = 0; j < 4; j++) {
            unsigned a0 = *(const unsigned*)&qs[r * QHS + j * 16 + tig * 2];
            unsigned a1 = *(const unsigned*)&qs[(r + 8) * QHS + j * 16 + tig * 2];
            unsigned a2 = *(const unsigned*)&qs[r * QHS + j * 16 + 8 + tig * 2];
            unsigned a3 = *(const unsigned*)&qs[(r + 8) * QHS + j * 16 + 8 + tig * 2];
            #pragma unroll
            for (int nt = 0; nt < 8; nt++) {
                const __half* krow = ks + (nt * 8 + gid) * QHS + j * 16 + tig * 2;
                unsigned b0 = *(const unsigned*)krow;
                unsigned b1 = *(const unsigned*)(krow + 8);
                mma_f16(sacc[nt], a0, a1, a2, a3, b0, b1);
            }
        }

        size_t mi = ((size_t)(b * HEADS + h)) * SEQ + q0 + wid * 16 + gid;
        float c0 = -lg2(g_l[mi]) - 4.0f;
        float c1 = -lg2(g_l[mi + 8]) - 4.0f;
        #pragma unroll
        for (int nt = 0; nt < 8; nt++) {
            amacc[nt][0] += ex2(sacc[nt][0] + c0);
            amacc[nt][1] += ex2(sacc[nt][1] + c0);
            amacc[nt][2] += ex2(sacc[nt][2] + c1);
            amacc[nt][3] += ex2(sacc[nt][3] + c1);
        }

        __syncthreads();
        if (h + 2 < HEADS) { issue_h(h + 2, h & 1); cp_wait1(); }
        else cp_wait0();
        __syncthreads();
    }

    const int row = q0 + wid * 16 + gid;
    float* arow = amean + ((size_t)b * SEQ + row) * SEQ + k0;
    #pragma unroll
    for (int nt = 0; nt < 8; nt++) {
        arow[nt * 8 + 2 * tig]               = amacc[nt][0];
        arow[nt * 8 + 2 * tig + 1]           = amacc[nt][1];
        arow[8 * SEQ + nt * 8 + 2 * tig]     = amacc[nt][2];
        arow[8 * SEQ + nt * 8 + 2 * tig + 1] = amacc[nt][3];
    }
}

// ================= tail: proj_out (256 blocks) + mean (1024 blocks) ==============
__global__ __launch_bounds__(256, 2) void tail_kernel(
    float* __restrict__ amean, const float* __restrict__ A,
    const float* __restrict__ W, const float* __restrict__ bias,
    float* __restrict__ C) {
    extern __shared__ float smem[];
    if (blockIdx.x < 256) {
        proj_out_body(smem, A, W, bias, C, blockIdx.x & 7, blockIdx.x >> 3);
    } else {
        int bx = blockIdx.x - 256;
        mean_body(smem, amean, bx & 31, (bx >> 5) & 15, bx >> 9);
    }
}

// ---------------- launch ------------------------------------------------------------
#define PROJ_SMEM (4 * 128 * PS * 4)
#define FLASH_SMEM ((128 * QHS + 2 * 64 * QHS + 2 * 64 * QHS) * 2)
#define MEAN_SMEM ((2 * 128 * QHS + 2 * 64 * QHS) * 2)
#define TAIL_SMEM (MEAN_SMEM > PROJ_SMEM ? MEAN_SMEM : PROJ_SMEM)

extern "C" void kernel_launch(void* const* d_in, const int* in_sizes, int n_in,
                              void* d_out, int out_size) {
    const float* x  = (const float*)d_in[0];
    const float* wq = (const float*)d_in[1];
    const float* bq = (const float*)d_in[2];
    const float* wk = (const float*)d_in[3];
    const float* bk = (const float*)d_in[4];
    const float* wv = (const float*)d_in[5];
    const float* bv = (const float*)d_in[6];
    const float* wo = (const float*)d_in[7];
    const float* bo = (const float*)d_in[8];

    float* out_o    = (float*)d_out;
    float* out_mean = out_o + (size_t)BS * DIM;

    static float* p_x = nullptr;
    static float* p_wo = nullptr;
    static float* p_ho = nullptr;
    if (!p_x) {
        cudaGetSymbolAddress((void**)&p_x, g_x);
        cudaGetSymbolAddress((void**)&p_wo, g_wo);
        cudaGetSymbolAddress((void**)&p_ho, g_ho);
        cudaFuncSetAttribute(proj_qkv,
                             cudaFuncAttributeMaxDynamicSharedMemorySize, PROJ_SMEM);
        cudaFuncSetAttribute(flash_kernel,
                             cudaFuncAttributeMaxDynamicSharedMemorySize, FLASH_SMEM);
        cudaFuncSetAttribute(tail_kernel,
                             cudaFuncAttributeMaxDynamicSharedMemorySize, TAIL_SMEM);
    }

    round_all<<<(NTOT4 + 255) / 256, 256>>>(x, wq, wk, wv, wo);

    proj_qkv<<<dim3(DIM / 128, BS / 128, 3), 256, PROJ_SMEM>>>(p_x, bq, bk, bv);

    flash_kernel<<<dim3(SEQ / 128, BATCH * HEADS), 256, FLASH_SMEM>>>();

    tail_kernel<<<256 + SEQ / 64 * (SEQ / 128) * BATCH, 256, TAIL_SMEM>>>(
        out_mean, p_ho, p_wo, bo, out_o);
}

// round 15
// speedup vs baseline: 1.9650x; 1.2982x over previous
#include <cuda_runtime.h>
#include <cuda_fp16.h>
#include <math.h>

#define BATCH 2
#define SEQ 2048
#define DIM 1024
#define HEADS 16
#define HEAD_DIM 64
#define BS (BATCH * SEQ)
#define QSCL 0.18033688011112042f   // 0.125 * log2(e)

// ---------------- scratch (static device memory; no allocations) ----------------
__device__ __half g_xh[BS * DIM];
__device__ __half g_wqh[DIM * DIM];
__device__ __half g_wkh[DIM * DIM];
__device__ __half g_wvh[DIM * DIM];
__device__ __half g_woh[DIM * DIM];
__device__ __half g_qh[BS * DIM];          // fp16 q, log2 domain (pre-scaled)
__device__ __half g_kh[BS * DIM];
__device__ __half g_vt[(size_t)BATCH * HEADS * HEAD_DIM * SEQ];  // V^T fp16
__device__ __half g_hoh[BS * DIM];         // attention output, fp16
__device__ float g_l[BATCH * HEADS * SEQ];

// ---------------- helpers --------------------------------------------------------
__device__ __forceinline__ float ex2(float x) {
    float r; asm("ex2.approx.ftz.f32 %0, %1;" : "=f"(r) : "f"(x)); return r;
}
__device__ __forceinline__ float lg2(float x) {
    float r; asm("lg2.approx.ftz.f32 %0, %1;" : "=f"(r) : "f"(x)); return r;
}
__device__ __forceinline__ unsigned packh(float hi, float lo) {
    unsigned r;
    asm("cvt.rn.f16x2.f32 %0, %1, %2;" : "=r"(r) : "f"(hi), "f"(lo));
    return r;
}

__device__ __forceinline__ void mma_f16(float c[4], unsigned a0, unsigned a1,
                                        unsigned a2, unsigned a3,
                                        unsigned b0, unsigned b1) {
    asm volatile(
        "mma.sync.aligned.m16n8k16.row.col.f32.f16.f16.f32 "
        "{%0,%1,%2,%3}, {%4,%5,%6,%7}, {%8,%9}, {%0,%1,%2,%3};"
        : "+f"(c[0]), "+f"(c[1]), "+f"(c[2]), "+f"(c[3])
        : "r"(a0), "r"(a1), "r"(a2), "r"(a3), "r"(b0), "r"(b1));
}

__device__ __forceinline__ void cp16(unsigned dst, const void* src) {
    asm volatile("cp.async.cg.shared.global [%0], [%1], 16;" :: "r"(dst), "l"(src));
}
__device__ __forceinline__ void cp_commit() {
    asm volatile("cp.async.commit_group;" ::: "memory");
}
__device__ __forceinline__ void cp_wait1() {
    asm volatile("cp.async.wait_group 1;" ::: "memory");
}
__device__ __forceinline__ void cp_wait0() {
    asm volatile("cp.async.wait_group 0;" ::: "memory");
}
__device__ __forceinline__ unsigned sptr(const void* p) {
    return (unsigned)__cvta_generic_to_shared(p);
}

// ================= prepass: fp16-convert all 5 tensors in one launch =============
#define NX4 (BS * DIM / 4)
#define NW4 (DIM * DIM / 4)         // 2^18
#define NTOT4 (NX4 + 4 * NW4)

__global__ __launch_bounds__(256) void round_all(
    const float* __restrict__ x,  const float* __restrict__ wq,
    const float* __restrict__ wk, const float* __restrict__ wv,
    const float* __restrict__ wo) {
    int i = blockIdx.x * 256 + threadIdx.x;
    if (i >= NTOT4) return;
    const float* src; __half* dst; int off;
    if (i < NX4) { src = x; dst = g_xh; off = i; }
    else {
        int j = i - NX4, w = j >> 18;
        off = j & (NW4 - 1);
        if (w == 0)      { src = wq; dst = g_wqh; }
        else if (w == 1) { src = wk; dst = g_wkh; }
        else if (w == 2) { src = wv; dst = g_wvh; }
        else             { src = wo; dst = g_woh; }
    }
    float4 v = ((const float4*)src)[off];
    __half2 h0 = __floats2half2_rn(v.x, v.y);
    __half2 h1 = __floats2half2_rn(v.z, v.w);
    ((__half2*)dst)[off * 2]     = h0;
    ((__half2*)dst)[off * 2 + 1] = h1;
}

// ================= fp16 GEMM tiles ===============================================
// BM=BN=128, BK=64 halves. Smem rows stride 72 halves (conflict-free pattern).
#define HS 72
#define HS32 36

// QKV fused projection. z==0: Q -> g_qh (scaled, log2). z==1: K -> g_kh.
// z==2: V -> g_vt fp16 transposed.
__global__ __launch_bounds__(256, 2) void proj_qkv(
    const float* __restrict__ bq, const float* __restrict__ bk,
    const float* __restrict__ bv) {
    extern __shared__ __half sm[];
    __half* As = sm;                    // 2 x [128][72]
    __half* Ws = sm + 2 * 128 * HS;     // 2 x [128][72]

    const int z = blockIdx.z;
    const __half* W; const float* bias; __half* Ch;
    if (z == 0)      { W = g_wqh; bias = bq; Ch = g_qh; }
    else if (z == 1) { W = g_wkh; bias = bk; Ch = g_kh; }
    else             { W = g_wvh; bias = bv; Ch = nullptr; }

    const int tid = threadIdx.x;
    const int wid = tid >> 5, lane = tid & 31;
    const int gid = lane >> 2, tig = lane & 3;
    const int wrow = wid & 3, wcol = wid >> 2;
    const int row0 = blockIdx.y * 128;
    const int col0 = blockIdx.x * 128;

    const unsigned asb = sptr(As), wsb = sptr(Ws);

    auto issue = [&](int t, int s) {
        const __half* ap = g_xh + (size_t)row0 * DIM + t * 64;
        const __half* wp = W + (size_t)col0 * DIM + t * 64;
        unsigned ad = asb + s * 128 * HS * 2;
        unsigned wd = wsb + s * 128 * HS * 2;
        #pragma unroll
        for (int i = tid; i < 1024; i += 256) {
            int r = i >> 3, c = i & 7;
            cp16(ad + r * HS * 2 + c * 16, ap + (size_t)r * DIM + c * 8);
            cp16(wd + r * HS * 2 + c * 16, wp + (size_t)r * DIM + c * 8);
        }
        cp_commit();
    };

    issue(0, 0);
    issue(1, 1);
    cp_wait1();
    __syncthreads();

    float acc[2][8][4];
    #pragma unroll
    for (int mt = 0; mt < 2; mt++)
        #pragma unroll
        for (int nt = 0; nt < 8; nt++)
            #pragma unroll
            for (int i = 0; i < 4; i++) acc[mt][nt][i] = 0.f;

    for (int it = 0; it < 16; it++) {
        const unsigned* as32 = (const unsigned*)(As + (it & 1) * 128 * HS);
        const unsigned* ws32 = (const unsigned*)(Ws + (it & 1) * 128 * HS);
        #pragma unroll
        for (int j = 0; j < 4; j++) {
            unsigned a[2][4];
            #pragma unroll
            for (int mt = 0; mt < 2; mt++) {
                int r = wrow * 32 + mt * 16 + gid;
                a[mt][0] = as32[r * HS32 + j * 8 + tig];
                a[mt][1] = as32[(r + 8) * HS32 + j * 8 + tig];
                a[mt][2] = as32[r * HS32 + j * 8 + 4 + tig];
                a[mt][3] = as32[(r + 8) * HS32 + j * 8 + 4 + tig];
            }
            #pragma unroll
            for (int nt = 0; nt < 8; nt++) {
                int n = wcol * 64 + nt * 8 + gid;
                unsigned b0 = ws32[n * HS32 + j * 8 + tig];
                unsigned b1 = ws32[n * HS32 + j * 8 + 4 + tig];
                mma_f16(acc[0][nt], a[0][0], a[0][1], a[0][2], a[0][3], b0, b1);
                mma_f16(acc[1][nt], a[1][0], a[1][1], a[1][2], a[1][3], b0, b1);
            }
        }
        __syncthreads();
        if (it + 2 < 16) { issue(it + 2, it & 1); cp_wait1(); }
        else cp_wait0();
        __syncthreads();
    }

    #pragma unroll
    for (int mt = 0; mt < 2; mt++) {
        #pragma unroll
        for (int nt = 0; nt < 8; nt++) {
            int m = row0 + wrow * 32 + mt * 16 + gid;
            int n = col0 + wcol * 64 + nt * 8 + tig * 2;
            float b0 = bias[n], b1 = bias[n + 1];
            float v0 = acc[mt][nt][0] + b0;
            float v1 = acc[mt][nt][1] + b1;
            float v2 = acc[mt][nt][2] + b0;
            float v3 = acc[mt][nt][3] + b1;
            if (z == 2) {
                int bb = m >> 11, s = m & (SEQ - 1);
                int h = n >> 6, d = n & 63;
                size_t base = ((size_t)(bb * HEADS + h) * HEAD_DIM + d) * SEQ;
                g_vt[base + s]           = __float2half(v0);
                g_vt[base + SEQ + s]     = __float2half(v1);
                g_vt[base + s + 8]       = __float2half(v2);
                g_vt[base + SEQ + s + 8] = __float2half(v3);
            } else {
                if (z == 0) { v0 *= QSCL; v1 *= QSCL; v2 *= QSCL; v3 *= QSCL; }
                Ch[(size_t)m * DIM + n]           = __float2half(v0);
                Ch[(size_t)m * DIM + n + 1]       = __float2half(v1);
                Ch[(size_t)(m + 8) * DIM + n]     = __float2half(v2);
                Ch[(size_t)(m + 8) * DIM + n + 1] = __float2half(v3);
            }
        }
    }
}

// Output projection body (fp16 inputs, fp32 final output).
__device__ __forceinline__ void proj_out_body(
    __half* sm, const float* __restrict__ bias, float* __restrict__ C,
    int bx, int by) {
    __half* As = sm;
    __half* Ws = sm + 2 * 128 * HS;

    const int tid = threadIdx.x;
    const int wid = tid >> 5, lane = tid & 31;
    const int gid = lane >> 2, tig = lane & 3;
    const int wrow = wid & 3, wcol = wid >> 2;
    const int row0 = by * 128;
    const int col0 = bx * 128;

    const unsigned asb = sptr(As), wsb = sptr(Ws);

    auto issue = [&](int t, int s) {
        const __half* ap = g_hoh + (size_t)row0 * DIM + t * 64;
        const __half* wp = g_woh + (size_t)col0 * DIM + t * 64;
        unsigned ad = asb + s * 128 * HS * 2;
        unsigned wd = wsb + s * 128 * HS * 2;
        #pragma unroll
        for (int i = tid; i < 1024; i += 256) {
            int r = i >> 3, c = i & 7;
            cp16(ad + r * HS * 2 + c * 16, ap + (size_t)r * DIM + c * 8);
            cp16(wd + r * HS * 2 + c * 16, wp + (size_t)r * DIM + c * 8);
        }
        cp_commit();
    };

    issue(0, 0);
    issue(1, 1);
    cp_wait1();
    __syncthreads();

    float acc[2][8][4];
    #pragma unroll
    for (int mt = 0; mt < 2; mt++)
        #pragma unroll
        for (int nt = 0; nt < 8; nt++)
            #pragma unroll
            for (int i = 0; i < 4; i++) acc[mt][nt][i] = 0.f;

    for (int it = 0; it < 16; it++) {
        const unsigned* as32 = (const unsigned*)(As + (it & 1) * 128 * HS);
        const unsigned* ws32 = (const unsigned*)(Ws + (it & 1) * 128 * HS);
        #pragma unroll
        for (int j = 0; j < 4; j++) {
            unsigned a[2][4];
            #pragma unroll
            for (int mt = 0; mt < 2; mt++) {
                int r = wrow * 32 + mt * 16 + gid;
                a[mt][0] = as32[r * HS32 + j * 8 + tig];
                a[mt][1] = as32[(r + 8) * HS32 + j * 8 + tig];
                a[mt][2] = as32[r * HS32 + j * 8 + 4 + tig];
                a[mt][3] = as32[(r + 8) * HS32 + j * 8 + 4 + tig];
            }
            #pragma unroll
            for (int nt = 0; nt < 8; nt++) {
                int n = wcol * 64 + nt * 8 + gid;
                unsigned b0 = ws32[n * HS32 + j * 8 + tig];
                unsigned b1 = ws32[n * HS32 + j * 8 + 4 + tig];
                mma_f16(acc[0][nt], a[0][0], a[0][1], a[0][2], a[0][3], b0, b1);
                mma_f16(acc[1][nt], a[1][0], a[1][1], a[1][2], a[1][3], b0, b1);
            }
        }
        __syncthreads();
        if (it + 2 < 16) { issue(it + 2, it & 1); cp_wait1(); }
        else cp_wait0();
        __syncthreads();
    }

    #pragma unroll
    for (int mt = 0; mt < 2; mt++) {
        #pragma unroll
        for (int nt = 0; nt < 8; nt++) {
            int m = row0 + wrow * 32 + mt * 16 + gid;
            int n = col0 + wcol * 64 + nt * 8 + tig * 2;
            float b0 = bias[n], b1 = bias[n + 1];
            C[(size_t)m * DIM + n]           = acc[mt][nt][0] + b0;
            C[(size_t)m * DIM + n + 1]       = acc[mt][nt][1] + b1;
            C[(size_t)(m + 8) * DIM + n]     = acc[mt][nt][2] + b0;
            C[(size_t)(m + 8) * DIM + n + 1] = acc[mt][nt][3] + b1;
        }
    }
}

// ================= fused flash attention: fp16 QK + fp16 PV ======================
__global__ __launch_bounds__(256, 2) void flash_kernel() {
    extern __shared__ __half smem_h[];
    __half* Qs = smem_h;                    // [128][72]
    __half* Ks = Qs + 128 * HS;             // 2 x [64][72]
    __half* Vt = Ks + 2 * 64 * HS;          // 2 x [64][72]

    const int tid = threadIdx.x;
    const int wid = tid >> 5, lane = tid & 31;
    const int gid = lane >> 2, tig = lane & 3;
    const int q0 = blockIdx.x * 128;
    const int bh = blockIdx.y;
    const int b = bh / HEADS, h = bh % HEADS;

    const __half* qbase = g_qh + ((size_t)b * SEQ + q0) * DIM + h * HEAD_DIM;
    const __half* kbase = g_kh + (size_t)b * SEQ * DIM + h * HEAD_DIM;
    const __half* vtbase = g_vt + (size_t)bh * HEAD_DIM * SEQ;

    const unsigned qsb = sptr(Qs), ksb = sptr(Ks), vsb = sptr(Vt);

    auto issue_kv = [&](int kt, int s) {
        const __half* kp = kbase + (size_t)kt * 64 * DIM;
        unsigned kd = ksb + s * 64 * HS * 2;
        #pragma unroll
        for (int i = tid; i < 512; i += 256) {
            int r = i >> 3, c = i & 7;
            cp16(kd + r * HS * 2 + c * 16, kp + (size_t)r * DIM + c * 8);
        }
        const __half* vp = vtbase + kt * 64;
        unsigned vd = vsb + s * 64 * HS * 2;
        #pragma unroll
        for (int i = tid; i < 512; i += 256) {
            int r = i >> 3, c = i & 7;
            cp16(vd + r * HS * 2 + c * 16, vp + (size_t)r * SEQ + c * 8);
        }
        cp_commit();
    };

    #pragma unroll
    for (int i = tid; i < 1024; i += 256) {
        int r = i >> 3, c = i & 7;
        cp16(qsb + r * HS * 2 + c * 16, qbase + (size_t)r * DIM + c * 8);
    }
    issue_kv(0, 0);
    issue_kv(1, 1);
    cp_wait1();
    __syncthreads();

    unsigned qa[4][4];
    {
        const unsigned* qs32 = (const unsigned*)Qs;
        int r = wid * 16 + gid;
        #pragma unroll
        for (int j = 0; j < 4; j++) {
            qa[j][0] = qs32[r * HS32 + j * 8 + tig];
            qa[j][1] = qs32[(r + 8) * HS32 + j * 8 + tig];
            qa[j][2] = qs32[r * HS32 + j * 8 + 4 + tig];
            qa[j][3] = qs32[(r + 8) * HS32 + j * 8 + 4 + tig];
        }
    }

    float oacc[8][4];
    #pragma unroll
    for (int nt = 0; nt < 8; nt++)
        #pragma unroll
        for (int i = 0; i < 4; i++) oacc[nt][i] = 0.f;
    float l0 = 0.f, l1 = 0.f;

    const int rowq = q0 + wid * 16 + gid;

    for (int kt = 0; kt < SEQ / 64; kt++) {
        const unsigned* ks32 = (const unsigned*)(Ks + (kt & 1) * 64 * HS);
        const unsigned* vs32 = (const unsigned*)(Vt + (kt & 1) * 64 * HS);

        float sacc[8][4];
        #pragma unroll
        for (int nt = 0; nt < 8; nt++)
            #pragma unroll
            for (int i = 0; i < 4; i++) sacc[nt][i] = 0.f;
        #pragma unroll
        for (int j = 0; j < 4; j++) {
            #pragma unroll
            for (int nt = 0; nt < 8; nt++) {
                unsigned b0 = ks32[(nt * 8 + gid) * HS32 + j * 8 + tig];
                unsigned b1 = ks32[(nt * 8 + gid) * HS32 + j * 8 + 4 + tig];
                mma_f16(sacc[nt], qa[j][0], qa[j][1], qa[j][2], qa[j][3], b0, b1);
            }
        }

        // ---- 2^s, denominators, pack P to f16x2 (A-fragment layout) ----
        unsigned pa0[8], pa1[8];
        #pragma unroll
        for (int nt = 0; nt < 8; nt++) {
            float p0 = ex2(sacc[nt][0]);
            float p1 = ex2(sacc[nt][1]);
            float p2 = ex2(sacc[nt][2]);
            float p3 = ex2(sacc[nt][3]);
            l0 += p0 + p1;  l1 += p2 + p3;
            pa0[nt] = packh(p1, p0);
            pa1[nt] = packh(p3, p2);
        }

        // ---- O += P * V via f16 m16n8k16 (no shuffles) ----
        #pragma unroll
        for (int j = 0; j < 4; j++) {
            unsigned a0 = pa0[2 * j],     a1 = pa1[2 * j];
            unsigned a2 = pa0[2 * j + 1], a3 = pa1[2 * j + 1];
            #pragma unroll
            for (int nt = 0; nt < 8; nt++) {
                unsigned b0 = vs32[(nt * 8 + gid) * HS32 + j * 8 + tig];
                unsigned b1 = vs32[(nt * 8 + gid) * HS32 + j * 8 + 4 + tig];
                mma_f16(oacc[nt], a0, a1, a2, a3, b0, b1);
            }
        }

        __syncthreads();
        if (kt + 2 < SEQ / 64) { issue_kv(kt + 2, kt & 1); cp_wait1(); }
        else cp_wait0();
        __syncthreads();
    }

    l0 += __shfl_xor_sync(~0u, l0, 1);
    l0 += __shfl_xor_sync(~0u, l0, 2);
    l1 += __shfl_xor_sync(~0u, l1, 1);
    l1 += __shfl_xor_sync(~0u, l1, 2);

    const float il0 = 1.f / l0, il1 = 1.f / l1;
    __half* orow = g_hoh + ((size_t)b * SEQ + rowq) * DIM + h * HEAD_DIM;
    #pragma unroll
    for (int nt = 0; nt < 8; nt++) {
        orow[nt * 8 + 2 * tig]               = __float2half(oacc[nt][0] * il0);
        orow[nt * 8 + 2 * tig + 1]           = __float2half(oacc[nt][1] * il0);
        orow[8 * DIM + nt * 8 + 2 * tig]     = __float2half(oacc[nt][2] * il1);
        orow[8 * DIM + nt * 8 + 2 * tig + 1] = __float2half(oacc[nt][3] * il1);
    }
    if (tig == 0) {
        size_t mi = (size_t)bh * SEQ + rowq;
        g_l[mi] = l0;
        g_l[mi + 8] = l1;
    }
}

// ================= head-mean body (fp16 QK recompute, m16n8k16) ==================
__device__ __forceinline__ void mean_body(__half* sm, float* __restrict__ amean,
                                          int bkx, int bqy, int b) {
    __half* Qh = sm;                     // 2 x [128][72]
    __half* Kh = Qh + 2 * 128 * HS;      // 2 x [64][72]

    const int tid = threadIdx.x;
    const int wid = tid >> 5, lane = tid & 31;
    const int gid = lane >> 2, tig = lane & 3;
    const int k0 = bkx * 64;
    const int q0 = bqy * 128;

    const __half* qbase = g_qh + ((size_t)b * SEQ + q0) * DIM;
    const __half* kbase = g_kh + ((size_t)b * SEQ + k0) * DIM;

    const unsigned qsb = sptr(Qh), ksb = sptr(Kh);

    auto issue_h = [&](int h, int s) {
        const __half* qp = qbase + h * HEAD_DIM;
        const __half* kp = kbase + h * HEAD_DIM;
        unsigned qd = qsb + s * 128 * HS * 2;
        unsigned kd = ksb + s * 64 * HS * 2;
        #pragma unroll
        for (int i = tid; i < 1024; i += 256) {
            int r = i >> 3, c = i & 7;
            cp16(qd + r * HS * 2 + c * 16, qp + (size_t)r * DIM + c * 8);
        }
        #pragma unroll
        for (int i = tid; i < 512; i += 256) {
            int r = i >> 3, c = i & 7;
            cp16(kd + r * HS * 2 + c * 16, kp + (size_t)r * DIM + c * 8);
        }
        cp_commit();
    };

    issue_h(0, 0);
    issue_h(1, 1);
    cp_wait1();
    __syncthreads();

    float amacc[8][4];
    #pragma unroll
    for (int nt = 0; nt < 8; nt++)
        #pragma unroll
        for (int i = 0; i < 4; i++) amacc[nt][i] = 0.f;

    for (int h = 0; h < HEADS; h++) {
        const unsigned* qs32 = (const unsigned*)(Qh + (h & 1) * 128 * HS);
        const unsigned* ks32 = (const unsigned*)(Kh + (h & 1) * 64 * HS);

        const int r = wid * 16 + gid;

        float sacc[8][4];
        #pragma unroll
        for (int nt = 0; nt < 8; nt++)
            #pragma unroll
            for (int i = 0; i < 4; i++) sacc[nt][i] = 0.f;

        #pragma unroll
        for (int j = 0; j < 4; j++) {
            unsigned a0 = qs32[r * HS32 + j * 8 + tig];
            unsigned a1 = qs32[(r + 8) * HS32 + j * 8 + tig];
            unsigned a2 = qs32[r * HS32 + j * 8 + 4 + tig];
            unsigned a3 = qs32[(r + 8) * HS32 + j * 8 + 4 + tig];
            #pragma unroll
            for (int nt = 0; nt < 8; nt++) {
                unsigned b0 = ks32[(nt * 8 + gid) * HS32 + j * 8 + tig];
                unsigned b1 = ks32[(nt * 8 + gid) * HS32 + j * 8 + 4 + tig];
                mma_f16(sacc[nt], a0, a1, a2, a3, b0, b1);
            }
        }

        size_t mi = ((size_t)(b * HEADS + h)) * SEQ + q0 + wid * 16 + gid;
        float c0 = -lg2(g_l[mi]) - 4.0f;
        float c1 = -lg2(g_l[mi + 8]) - 4.0f;
        #pragma unroll
        for (int nt = 0; nt < 8; nt++) {
            amacc[nt][0] += ex2(sacc[nt][0] + c0);
            amacc[nt][1] += ex2(sacc[nt][1] + c0);
            amacc[nt][2] += ex2(sacc[nt][2] + c1);
            amacc[nt][3] += ex2(sacc[nt][3] + c1);
        }

        __syncthreads();
        if (h + 2 < HEADS) { issue_h(h + 2, h & 1); cp_wait1(); }
        else cp_wait0();
        __syncthreads();
    }

    const int row = q0 + wid * 16 + gid;
    float* arow = amean + ((size_t)b * SEQ + row) * SEQ + k0;
    #pragma unroll
    for (int nt = 0; nt < 8; nt++) {
        arow[nt * 8 + 2 * tig]               = amacc[nt][0];
        arow[nt * 8 + 2 * tig + 1]           = amacc[nt][1];
        arow[8 * SEQ + nt * 8 + 2 * tig]     = amacc[nt][2];
        arow[8 * SEQ + nt * 8 + 2 * tig + 1] = amacc[nt][3];
    }
}

// ================= tail: proj_out (256 blocks) + mean (1024 blocks) ==============
__global__ __launch_bounds__(256, 2) void tail_kernel(
    float* __restrict__ amean, const float* __restrict__ bias,
    float* __restrict__ C) {
    extern __shared__ __half sm[];
    if (blockIdx.x < 256) {
        proj_out_body(sm, bias, C, blockIdx.x & 7, blockIdx.x >> 3);
    } else {
        int bx = blockIdx.x - 256;
        mean_body(sm, amean, bx & 31, (bx >> 5) & 15, bx >> 9);
    }
}

// ---------------- launch ------------------------------------------------------------
#define PROJ_SMEM (4 * 128 * HS * 2)                   // 73728
#define FLASH_SMEM ((128 + 128 + 128) * HS * 2)        // 55296
#define MEAN_SMEM ((2 * 128 + 2 * 64) * HS * 2)        // 55296
#define TAIL_SMEM (MEAN_SMEM > PROJ_SMEM ? MEAN_SMEM : PROJ_SMEM)

extern "C" void kernel_launch(void* const* d_in, const int* in_sizes, int n_in,
                              void* d_out, int out_size) {
    const float* x  = (const float*)d_in[0];
    const float* wq = (const float*)d_in[1];
    const float* bq = (const float*)d_in[2];
    const float* wk = (const float*)d_in[3];
    const float* bk = (const float*)d_in[4];
    const float* wv = (const float*)d_in[5];
    const float* bv = (const float*)d_in[6];
    const float* wo = (const float*)d_in[7];
    const float* bo = (const float*)d_in[8];

    float* out_o    = (float*)d_out;
    float* out_mean = out_o + (size_t)BS * DIM;

    static bool init = false;
    if (!init) {
        init = true;
        cudaFuncSetAttribute(proj_qkv,
                             cudaFuncAttributeMaxDynamicSharedMemorySize, PROJ_SMEM);
        cudaFuncSetAttribute(flash_kernel,
                             cudaFuncAttributeMaxDynamicSharedMemorySize, FLASH_SMEM);
        cudaFuncSetAttribute(tail_kernel,
                             cudaFuncAttributeMaxDynamicSharedMemorySize, TAIL_SMEM);
    }

    round_all<<<(NTOT4 + 255) / 256, 256>>>(x, wq, wk, wv, wo);

    proj_qkv<<<dim3(DIM / 128, BS / 128, 3), 256, PROJ_SMEM>>>(bq, bk, bv);

    flash_kernel<<<dim3(SEQ / 128, BATCH * HEADS), 256, FLASH_SMEM>>>();

    tail_kernel<<<256 + SEQ / 64 * (SEQ / 128) * BATCH, 256, TAIL_SMEM>>>(
        out_mean, bo, out_o);
}

// round 17
// speedup vs baseline: 1.9870x; 1.0112x over previous
#include <cuda_runtime.h>
#include <cuda_fp16.h>
#include <math.h>

#define BATCH 2
#define SEQ 2048
#define DIM 1024
#define HEADS 16
#define HEAD_DIM 64
#define BS (BATCH * SEQ)
#define QSCL 0.18033688011112042f   // 0.125 * log2(e)

// ---------------- scratch (static device memory; no allocations) ----------------
__device__ __half g_xh[BS * DIM];
__device__ __half g_wqh[DIM * DIM];
__device__ __half g_wkh[DIM * DIM];
__device__ __half g_wvh[DIM * DIM];
__device__ __half g_woh[DIM * DIM];
__device__ __half g_qh[BS * DIM];          // fp16 q, log2 domain (pre-scaled)
__device__ __half g_kh[BS * DIM];
__device__ __half g_vt[(size_t)BATCH * HEADS * HEAD_DIM * SEQ];  // V^T fp16
__device__ __half g_hoh[BS * DIM];         // attention output, fp16
__device__ float g_l[BATCH * HEADS * SEQ];

// ---------------- helpers --------------------------------------------------------
__device__ __forceinline__ float ex2(float x) {
    float r; asm("ex2.approx.ftz.f32 %0, %1;" : "=f"(r) : "f"(x)); return r;
}
__device__ __forceinline__ float lg2(float x) {
    float r; asm("lg2.approx.ftz.f32 %0, %1;" : "=f"(r) : "f"(x)); return r;
}
__device__ __forceinline__ unsigned packh(float hi, float lo) {
    unsigned r;
    asm("cvt.rn.f16x2.f32 %0, %1, %2;" : "=r"(r) : "f"(hi), "f"(lo));
    return r;
}

__device__ __forceinline__ void mma_f16(float c[4], unsigned a0, unsigned a1,
                                        unsigned a2, unsigned a3,
                                        unsigned b0, unsigned b1) {
    asm volatile(
        "mma.sync.aligned.m16n8k16.row.col.f32.f16.f16.f32 "
        "{%0,%1,%2,%3}, {%4,%5,%6,%7}, {%8,%9}, {%0,%1,%2,%3};"
        : "+f"(c[0]), "+f"(c[1]), "+f"(c[2]), "+f"(c[3])
        : "r"(a0), "r"(a1), "r"(a2), "r"(a3), "r"(b0), "r"(b1));
}

__device__ __forceinline__ void cp16(unsigned dst, const void* src) {
    asm volatile("cp.async.cg.shared.global [%0], [%1], 16;" :: "r"(dst), "l"(src));
}
__device__ __forceinline__ void cp_commit() {
    asm volatile("cp.async.commit_group;" ::: "memory");
}
__device__ __forceinline__ void cp_wait1() {
    asm volatile("cp.async.wait_group 1;" ::: "memory");
}
__device__ __forceinline__ void cp_wait0() {
    asm volatile("cp.async.wait_group 0;" ::: "memory");
}
__device__ __forceinline__ unsigned sptr(const void* p) {
    return (unsigned)__cvta_generic_to_shared(p);
}

// ================= prepass: fp16-convert all 5 tensors in one launch =============
#define NX4 (BS * DIM / 4)
#define NW4 (DIM * DIM / 4)         // 2^18
#define NTOT4 (NX4 + 4 * NW4)

__global__ __launch_bounds__(256) void round_all(
    const float* __restrict__ x,  const float* __restrict__ wq,
    const float* __restrict__ wk, const float* __restrict__ wv,
    const float* __restrict__ wo) {
    int i = blockIdx.x * 256 + threadIdx.x;
    if (i >= NTOT4) return;
    const float* src; __half* dst; int off;
    if (i < NX4) { src = x; dst = g_xh; off = i; }
    else {
        int j = i - NX4, w = j >> 18;
        off = j & (NW4 - 1);
        if (w == 0)      { src = wq; dst = g_wqh; }
        else if (w == 1) { src = wk; dst = g_wkh; }
        else if (w == 2) { src = wv; dst = g_wvh; }
        else             { src = wo; dst = g_woh; }
    }
    float4 v = ((const float4*)src)[off];
    __half2 h0 = __floats2half2_rn(v.x, v.y);
    __half2 h1 = __floats2half2_rn(v.z, v.w);
    ((__half2*)dst)[off * 2]     = h0;
    ((__half2*)dst)[off * 2 + 1] = h1;
}

// ================= fp16 GEMM tiles ===============================================
// BM=BN=128, BK=64 halves; 3-stage cp.async pipeline, ONE sync per iteration.
#define HS 72
#define HS32 36

// QKV fused projection. z==0: Q -> g_qh (scaled, log2). z==1: K -> g_kh.
// z==2: V -> g_vt fp16 transposed.
__global__ __launch_bounds__(256, 2) void proj_qkv(
    const float* __restrict__ bq, const float* __restrict__ bk,
    const float* __restrict__ bv) {
    extern __shared__ __half sm[];
    __half* As = sm;                    // 3 x [128][72]
    __half* Ws = sm + 3 * 128 * HS;     // 3 x [128][72]

    const int z = blockIdx.z;
    const __half* W; const float* bias; __half* Ch;
    if (z == 0)      { W = g_wqh; bias = bq; Ch = g_qh; }
    else if (z == 1) { W = g_wkh; bias = bk; Ch = g_kh; }
    else             { W = g_wvh; bias = bv; Ch = nullptr; }

    const int tid = threadIdx.x;
    const int wid = tid >> 5, lane = tid & 31;
    const int gid = lane >> 2, tig = lane & 3;
    const int wrow = wid & 3, wcol = wid >> 2;
    const int row0 = blockIdx.y * 128;
    const int col0 = blockIdx.x * 128;

    const unsigned asb = sptr(As), wsb = sptr(Ws);

    auto issue = [&](int t) {
        int s = t % 3;
        const __half* ap = g_xh + (size_t)row0 * DIM + t * 64;
        const __half* wp = W + (size_t)col0 * DIM + t * 64;
        unsigned ad = asb + s * 128 * HS * 2;
        unsigned wd = wsb + s * 128 * HS * 2;
        #pragma unroll
        for (int i = tid; i < 1024; i += 256) {
            int r = i >> 3, c = i & 7;
            cp16(ad + r * HS * 2 + c * 16, ap + (size_t)r * DIM + c * 8);
            cp16(wd + r * HS * 2 + c * 16, wp + (size_t)r * DIM + c * 8);
        }
        cp_commit();
    };

    issue(0);
    issue(1);

    float acc[2][8][4];
    #pragma unroll
    for (int mt = 0; mt < 2; mt++)
        #pragma unroll
        for (int nt = 0; nt < 8; nt++)
            #pragma unroll
            for (int i = 0; i < 4; i++) acc[mt][nt][i] = 0.f;

    for (int it = 0; it < 16; it++) {
        if (it + 1 < 16) cp_wait1(); else cp_wait0();
        __syncthreads();
        if (it + 2 < 16) issue(it + 2);

        int s = it % 3;
        const unsigned* as32 = (const unsigned*)(As + s * 128 * HS);
        const unsigned* ws32 = (const unsigned*)(Ws + s * 128 * HS);
        #pragma unroll
        for (int j = 0; j < 4; j++) {
            unsigned a[2][4];
            #pragma unroll
            for (int mt = 0; mt < 2; mt++) {
                int r = wrow * 32 + mt * 16 + gid;
                a[mt][0] = as32[r * HS32 + j * 8 + tig];
                a[mt][1] = as32[(r + 8) * HS32 + j * 8 + tig];
                a[mt][2] = as32[r * HS32 + j * 8 + 4 + tig];
                a[mt][3] = as32[(r + 8) * HS32 + j * 8 + 4 + tig];
            }
            #pragma unroll
            for (int nt = 0; nt < 8; nt++) {
                int n = wcol * 64 + nt * 8 + gid;
                unsigned b0 = ws32[n * HS32 + j * 8 + tig];
                unsigned b1 = ws32[n * HS32 + j * 8 + 4 + tig];
                mma_f16(acc[0][nt], a[0][0], a[0][1], a[0][2], a[0][3], b0, b1);
                mma_f16(acc[1][nt], a[1][0], a[1][1], a[1][2], a[1][3], b0, b1);
            }
        }
    }

    #pragma unroll
    for (int mt = 0; mt < 2; mt++) {
        #pragma unroll
        for (int nt = 0; nt < 8; nt++) {
            int m = row0 + wrow * 32 + mt * 16 + gid;
            int n = col0 + wcol * 64 + nt * 8 + tig * 2;
            float b0 = bias[n], b1 = bias[n + 1];
            float v0 = acc[mt][nt][0] + b0;
            float v1 = acc[mt][nt][1] + b1;
            float v2 = acc[mt][nt][2] + b0;
            float v3 = acc[mt][nt][3] + b1;
            if (z == 2) {
                int bb = m >> 11, s = m & (SEQ - 1);
                int h = n >> 6, d = n & 63;
                size_t base = ((size_t)(bb * HEADS + h) * HEAD_DIM + d) * SEQ;
                g_vt[base + s]           = __float2half(v0);
                g_vt[base + SEQ + s]     = __float2half(v1);
                g_vt[base + s + 8]       = __float2half(v2);
                g_vt[base + SEQ + s + 8] = __float2half(v3);
            } else {
                if (z == 0) { v0 *= QSCL; v1 *= QSCL; v2 *= QSCL; v3 *= QSCL; }
                Ch[(size_t)m * DIM + n]           = __float2half(v0);
                Ch[(size_t)m * DIM + n + 1]       = __float2half(v1);
                Ch[(size_t)(m + 8) * DIM + n]     = __float2half(v2);
                Ch[(size_t)(m + 8) * DIM + n + 1] = __float2half(v3);
            }
        }
    }
}

// Output projection body (fp16 inputs, fp32 final output), 3-stage pipeline.
__device__ __forceinline__ void proj_out_body(
    __half* sm, const float* __restrict__ bias, float* __restrict__ C,
    int bx, int by) {
    __half* As = sm;
    __half* Ws = sm + 3 * 128 * HS;

    const int tid = threadIdx.x;
    const int wid = tid >> 5, lane = tid & 31;
    const int gid = lane >> 2, tig = lane & 3;
    const int wrow = wid & 3, wcol = wid >> 2;
    const int row0 = by * 128;
    const int col0 = bx * 128;

    const unsigned asb = sptr(As), wsb = sptr(Ws);

    auto issue = [&](int t) {
        int s = t % 3;
        const __half* ap = g_hoh + (size_t)row0 * DIM + t * 64;
        const __half* wp = g_woh + (size_t)col0 * DIM + t * 64;
        unsigned ad = asb + s * 128 * HS * 2;
        unsigned wd = wsb + s * 128 * HS * 2;
        #pragma unroll
        for (int i = tid; i < 1024; i += 256) {
            int r = i >> 3, c = i & 7;
            cp16(ad + r * HS * 2 + c * 16, ap + (size_t)r * DIM + c * 8);
            cp16(wd + r * HS * 2 + c * 16, wp + (size_t)r * DIM + c * 8);
        }
        cp_commit();
    };

    issue(0);
    issue(1);

    float acc[2][8][4];
    #pragma unroll
    for (int mt = 0; mt < 2; mt++)
        #pragma unroll
        for (int nt = 0; nt < 8; nt++)
            #pragma unroll
            for (int i = 0; i < 4; i++) acc[mt][nt][i] = 0.f;

    for (int it = 0; it < 16; it++) {
        if (it + 1 < 16) cp_wait1(); else cp_wait0();
        __syncthreads();
        if (it + 2 < 16) issue(it + 2);

        int s = it % 3;
        const unsigned* as32 = (const unsigned*)(As + s * 128 * HS);
        const unsigned* ws32 = (const unsigned*)(Ws + s * 128 * HS);
        #pragma unroll
        for (int j = 0; j < 4; j++) {
            unsigned a[2][4];
            #pragma unroll
            for (int mt = 0; mt < 2; mt++) {
                int r = wrow * 32 + mt * 16 + gid;
                a[mt][0] = as32[r * HS32 + j * 8 + tig];
                a[mt][1] = as32[(r + 8) * HS32 + j * 8 + tig];
                a[mt][2] = as32[r * HS32 + j * 8 + 4 + tig];
                a[mt][3] = as32[(r + 8) * HS32 + j * 8 + 4 + tig];
            }
            #pragma unroll
            for (int nt = 0; nt < 8; nt++) {
                int n = wcol * 64 + nt * 8 + gid;
                unsigned b0 = ws32[n * HS32 + j * 8 + tig];
                unsigned b1 = ws32[n * HS32 + j * 8 + 4 + tig];
                mma_f16(acc[0][nt], a[0][0], a[0][1], a[0][2], a[0][3], b0, b1);
                mma_f16(acc[1][nt], a[1][0], a[1][1], a[1][2], a[1][3], b0, b1);
            }
        }
    }

    #pragma unroll
    for (int mt = 0; mt < 2; mt++) {
        #pragma unroll
        for (int nt = 0; nt < 8; nt++) {
            int m = row0 + wrow * 32 + mt * 16 + gid;
            int n = col0 + wcol * 64 + nt * 8 + tig * 2;
            float b0 = bias[n], b1 = bias[n + 1];
            C[(size_t)m * DIM + n]           = acc[mt][nt][0] + b0;
            C[(size_t)m * DIM + n + 1]       = acc[mt][nt][1] + b1;
            C[(size_t)(m + 8) * DIM + n]     = acc[mt][nt][2] + b0;
            C[(size_t)(m + 8) * DIM + n + 1] = acc[mt][nt][3] + b1;
        }
    }
}

// ================= fused flash attention: fp16 QK + fp16 PV, 3-stage =============
__global__ __launch_bounds__(256, 2) void flash_kernel() {
    extern __shared__ __half smem_h[];
    __half* Qs = smem_h;                    // [128][72]
    __half* Ks = Qs + 128 * HS;             // 3 x [64][72]
    __half* Vt = Ks + 3 * 64 * HS;          // 3 x [64][72]

    const int tid = threadIdx.x;
    const int wid = tid >> 5, lane = tid & 31;
    const int gid = lane >> 2, tig = lane & 3;
    const int q0 = blockIdx.x * 128;
    const int bh = blockIdx.y;
    const int b = bh / HEADS, h = bh % HEADS;

    const __half* qbase = g_qh + ((size_t)b * SEQ + q0) * DIM + h * HEAD_DIM;
    const __half* kbase = g_kh + (size_t)b * SEQ * DIM + h * HEAD_DIM;
    const __half* vtbase = g_vt + (size_t)bh * HEAD_DIM * SEQ;

    const unsigned qsb = sptr(Qs), ksb = sptr(Ks), vsb = sptr(Vt);

    auto issue_kv = [&](int kt) {
        int s = kt % 3;
        const __half* kp = kbase + (size_t)kt * 64 * DIM;
        unsigned kd = ksb + s * 64 * HS * 2;
        #pragma unroll
        for (int i = tid; i < 512; i += 256) {
            int r = i >> 3, c = i & 7;
            cp16(kd + r * HS * 2 + c * 16, kp + (size_t)r * DIM + c * 8);
        }
        const __half* vp = vtbase + kt * 64;
        unsigned vd = vsb + s * 64 * HS * 2;
        #pragma unroll
        for (int i = tid; i < 512; i += 256) {
            int r = i >> 3, c = i & 7;
            cp16(vd + r * HS * 2 + c * 16, vp + (size_t)r * SEQ + c * 8);
        }
        cp_commit();
    };

    // group 0: Q + KV(0); group 1: KV(1)
    #pragma unroll
    for (int i = tid; i < 1024; i += 256) {
        int r = i >> 3, c = i & 7;
        cp16(qsb + r * HS * 2 + c * 16, qbase + (size_t)r * DIM + c * 8);
    }
    issue_kv(0);
    issue_kv(1);

    cp_wait1();
    __syncthreads();

    unsigned qa[4][4];
    {
        const unsigned* qs32 = (const unsigned*)Qs;
        int r = wid * 16 + gid;
        #pragma unroll
        for (int j = 0; j < 4; j++) {
            qa[j][0] = qs32[r * HS32 + j * 8 + tig];
            qa[j][1] = qs32[(r + 8) * HS32 + j * 8 + tig];
            qa[j][2] = qs32[r * HS32 + j * 8 + 4 + tig];
            qa[j][3] = qs32[(r + 8) * HS32 + j * 8 + 4 + tig];
        }
    }

    float oacc[8][4];
    #pragma unroll
    for (int nt = 0; nt < 8; nt++)
        #pragma unroll
        for (int i = 0; i < 4; i++) oacc[nt][i] = 0.f;
    float l0 = 0.f, l1 = 0.f;

    const int rowq = q0 + wid * 16 + gid;
    const int NKT = SEQ / 64;

    for (int kt = 0; kt < NKT; kt++) {
        // stage kt is complete (wait done for kt=0 above; below for kt>0)
        if (kt + 2 < NKT) issue_kv(kt + 2);

        int s = kt % 3;
        const unsigned* ks32 = (const unsigned*)(Ks + s * 64 * HS);
        const unsigned* vs32 = (const unsigned*)(Vt + s * 64 * HS);

        float sacc[8][4];
        #pragma unroll
        for (int nt = 0; nt < 8; nt++)
            #pragma unroll
            for (int i = 0; i < 4; i++) sacc[nt][i] = 0.f;
        #pragma unroll
        for (int j = 0; j < 4; j++) {
            #pragma unroll
            for (int nt = 0; nt < 8; nt++) {
                unsigned b0 = ks32[(nt * 8 + gid) * HS32 + j * 8 + tig];
                unsigned b1 = ks32[(nt * 8 + gid) * HS32 + j * 8 + 4 + tig];
                mma_f16(sacc[nt], qa[j][0], qa[j][1], qa[j][2], qa[j][3], b0, b1);
            }
        }

        unsigned pa0[8], pa1[8];
        #pragma unroll
        for (int nt = 0; nt < 8; nt++) {
            float p0 = ex2(sacc[nt][0]);
            float p1 = ex2(sacc[nt][1]);
            float p2 = ex2(sacc[nt][2]);
            float p3 = ex2(sacc[nt][3]);
            l0 += p0 + p1;  l1 += p2 + p3;
            pa0[nt] = packh(p1, p0);
            pa1[nt] = packh(p3, p2);
        }

        #pragma unroll
        for (int j = 0; j < 4; j++) {
            unsigned a0 = pa0[2 * j],     a1 = pa1[2 * j];
            unsigned a2 = pa0[2 * j + 1], a3 = pa1[2 * j + 1];
            #pragma unroll
            for (int nt = 0; nt < 8; nt++) {
                unsigned b0 = vs32[(nt * 8 + gid) * HS32 + j * 8 + tig];
                unsigned b1 = vs32[(nt * 8 + gid) * HS32 + j * 8 + 4 + tig];
                mma_f16(oacc[nt], a0, a1, a2, a3, b0, b1);
            }
        }

        if (kt + 1 < NKT) {
            if (kt + 2 < NKT) cp_wait1(); else cp_wait0();
            __syncthreads();
        }
    }

    l0 += __shfl_xor_sync(~0u, l0, 1);
    l0 += __shfl_xor_sync(~0u, l0, 2);
    l1 += __shfl_xor_sync(~0u, l1, 1);
    l1 += __shfl_xor_sync(~0u, l1, 2);

    const float il0 = 1.f / l0, il1 = 1.f / l1;
    __half* orow = g_hoh + ((size_t)b * SEQ + rowq) * DIM + h * HEAD_DIM;
    #pragma unroll
    for (int nt = 0; nt < 8; nt++) {
        orow[nt * 8 + 2 * tig]               = __float2half(oacc[nt][0] * il0);
        orow[nt * 8 + 2 * tig + 1]           = __float2half(oacc[nt][1] * il0);
        orow[8 * DIM + nt * 8 + 2 * tig]     = __float2half(oacc[nt][2] * il1);
        orow[8 * DIM + nt * 8 + 2 * tig + 1] = __float2half(oacc[nt][3] * il1);
    }
    if (tig == 0) {
        size_t mi = (size_t)bh * SEQ + rowq;
        g_l[mi] = l0;
        g_l[mi + 8] = l1;
    }
}

// ================= head-mean body (fp16 QK recompute, 3-stage) ===================
__device__ __forceinline__ void mean_body(__half* sm, float* __restrict__ amean,
                                          int bkx, int bqy, int b) {
    __half* Qh = sm;                     // 3 x [128][72]
    __half* Kh = Qh + 3 * 128 * HS;      // 3 x [64][72]

    const int tid = threadIdx.x;
    const int wid = tid >> 5, lane = tid & 31;
    const int gid = lane >> 2, tig = lane & 3;
    const int k0 = bkx * 64;
    const int q0 = bqy * 128;

    const __half* qbase = g_qh + ((size_t)b * SEQ + q0) * DIM;
    const __half* kbase = g_kh + ((size_t)b * SEQ + k0) * DIM;

    const unsigned qsb = sptr(Qh), ksb = sptr(Kh);

    auto issue_h = [&](int h) {
        int s = h % 3;
        const __half* qp = qbase + h * HEAD_DIM;
        const __half* kp = kbase + h * HEAD_DIM;
        unsigned qd = qsb + s * 128 * HS * 2;
        unsigned kd = ksb + s * 64 * HS * 2;
        #pragma unroll
        for (int i = tid; i < 1024; i += 256) {
            int r = i >> 3, c = i & 7;
            cp16(qd + r * HS * 2 + c * 16, qp + (size_t)r * DIM + c * 8);
        }
        #pragma unroll
        for (int i = tid; i < 512; i += 256) {
            int r = i >> 3, c = i & 7;
            cp16(kd + r * HS * 2 + c * 16, kp + (size_t)r * DIM + c * 8);
        }
        cp_commit();
    };

    issue_h(0);
    issue_h(1);

    float amacc[8][4];
    #pragma unroll
    for (int nt = 0; nt < 8; nt++)
        #pragma unroll
        for (int i = 0; i < 4; i++) amacc[nt][i] = 0.f;

    for (int h = 0; h < HEADS; h++) {
        if (h + 1 < HEADS) cp_wait1(); else cp_wait0();
        __syncthreads();
        if (h + 2 < HEADS) issue_h(h + 2);

        int s = h % 3;
        const unsigned* qs32 = (const unsigned*)(Qh + s * 128 * HS);
        const unsigned* ks32 = (const unsigned*)(Kh + s * 64 * HS);

        const int r = wid * 16 + gid;

        float sacc[8][4];
        #pragma unroll
        for (int nt = 0; nt < 8; nt++)
            #pragma unroll
            for (int i = 0; i < 4; i++) sacc[nt][i] = 0.f;

        #pragma unroll
        for (int j = 0; j < 4; j++) {
            unsigned a0 = qs32[r * HS32 + j * 8 + tig];
            unsigned a1 = qs32[(r + 8) * HS32 + j * 8 + tig];
            unsigned a2 = qs32[r * HS32 + j * 8 + 4 + tig];
            unsigned a3 = qs32[(r + 8) * HS32 + j * 8 + 4 + tig];
            #pragma unroll
            for (int nt = 0; nt < 8; nt++) {
                unsigned b0 = ks32[(nt * 8 + gid) * HS32 + j * 8 + tig];
                unsigned b1 = ks32[(nt * 8 + gid) * HS32 + j * 8 + 4 + tig];
                mma_f16(sacc[nt], a0, a1, a2, a3, b0, b1);
            }
        }

        size_t mi = ((size_t)(b * HEADS + h)) * SEQ + q0 + wid * 16 + gid;
        float c0 = -lg2(g_l[mi]) - 4.0f;
        float c1 = -lg2(g_l[mi + 8]) - 4.0f;
        #pragma unroll
        for (int nt = 0; nt < 8; nt++) {
            amacc[nt][0] += ex2(sacc[nt][0] + c0);
            amacc[nt][1] += ex2(sacc[nt][1] + c0);
            amacc[nt][2] += ex2(sacc[nt][2] + c1);
            amacc[nt][3] += ex2(sacc[nt][3] + c1);
        }
    }

    const int row = q0 + wid * 16 + gid;
    float* arow = amean + ((size_t)b * SEQ + row) * SEQ + k0;
    #pragma unroll
    for (int nt = 0; nt < 8; nt++) {
        arow[nt * 8 + 2 * tig]               = amacc[nt][0];
        arow[nt * 8 + 2 * tig + 1]           = amacc[nt][1];
        arow[8 * SEQ + nt * 8 + 2 * tig]     = amacc[nt][2];
        arow[8 * SEQ + nt * 8 + 2 * tig + 1] = amacc[nt][3];
    }
}

// ================= tail: proj_out (256 blocks) + mean (1024 blocks) ==============
__global__ __launch_bounds__(256, 2) void tail_kernel(
    float* __restrict__ amean, const float* __restrict__ bias,
    float* __restrict__ C) {
    extern __shared__ __half sm[];
    if (blockIdx.x < 256) {
        proj_out_body(sm, bias, C, blockIdx.x & 7, blockIdx.x >> 3);
    } else {
        int bx = blockIdx.x - 256;
        mean_body(sm, amean, bx & 31, (bx >> 5) & 15, bx >> 9);
    }
}

// ---------------- launch ------------------------------------------------------------
#define PROJ_SMEM (6 * 128 * HS * 2)                   // 110592
#define FLASH_SMEM ((128 + 3 * 64 + 3 * 64) * HS * 2)  // 73728
#define MEAN_SMEM ((3 * 128 + 3 * 64) * HS * 2)        // 82944
#define TAIL_SMEM (PROJ_SMEM > MEAN_SMEM ? PROJ_SMEM : MEAN_SMEM)

extern "C" void kernel_launch(void* const* d_in, const int* in_sizes, int n_in,
                              void* d_out, int out_size) {
    const float* x  = (const float*)d_in[0];
    const float* wq = (const float*)d_in[1];
    const float* bq = (const float*)d_in[2];
    const float* wk = (const float*)d_in[3];
    const float* bk = (const float*)d_in[4];
    const float* wv = (const float*)d_in[5];
    const float* bv = (const float*)d_in[6];
    const float* wo = (const float*)d_in[7];
    const float* bo = (const float*)d_in[8];

    float* out_o    = (float*)d_out;
    float* out_mean = out_o + (size_t)BS * DIM;

    static bool init = false;
    if (!init) {
        init = true;
        cudaFuncSetAttribute(proj_qkv,
                             cudaFuncAttributeMaxDynamicSharedMemorySize, PROJ_SMEM);
        cudaFuncSetAttribute(flash_kernel,
                             cudaFuncAttributeMaxDynamicSharedMemorySize, FLASH_SMEM);
        cudaFuncSetAttribute(tail_kernel,
                             cudaFuncAttributeMaxDynamicSharedMemorySize, TAIL_SMEM);
    }

    round_all<<<(NTOT4 + 255) / 256, 256>>>(x, wq, wk, wv, wo);

    proj_qkv<<<dim3(DIM / 128, BS / 128, 3), 256, PROJ_SMEM>>>(bq, bk, bv);

    flash_kernel<<<dim3(SEQ / 128, BATCH * HEADS), 256, FLASH_SMEM>>>();

    tail_kernel<<<256 + SEQ / 64 * (SEQ / 128) * BATCH, 256, TAIL_SMEM>>>(
        out_mean, bo, out_o);
}